// round 10
// baseline (speedup 1.0000x reference)
#include <cuda_runtime.h>
#include <math.h>
#include <stdint.h>

// Problem constants
constexpr int kT = 4096;
constexpr int kC = 2048;
constexpr int kH = 16;
constexpr int kD = 128;
constexpr float kScale = 0.08838834764831845f;

// Scratch (device globals — no cudaMalloc allowed)
__device__ float g_q[kT * kC];
__device__ float g_k[kT * kC];
__device__ float g_v[kT * kC];
__device__ float g_ctx[kT * kC];
__device__ float g_xr[kT * kC];          // tf32-rounded x
__device__ float g_wr[4 * kC * kC];      // tf32-rounded wq,wk,wv,wo

// ---------------------------------------------------------------------------
__device__ __forceinline__ uint32_t smem_u32(const void* p) {
    uint32_t a;
    asm("{ .reg .u64 t; cvta.to.shared.u64 t, %1; cvt.u32.u64 %0, t; }"
        : "=r"(a) : "l"(p));
    return a;
}

__device__ __forceinline__ void cp_async16(uint32_t saddr, const void* gaddr) {
    asm volatile("cp.async.cg.shared.global [%0], [%1], 16;"
                 :: "r"(saddr), "l"(gaddr));
}
#define CP_COMMIT() asm volatile("cp.async.commit_group;" ::: "memory")

__device__ __forceinline__ float round_tf32(float x) {
    uint32_t u;
    asm("cvt.rna.tf32.f32 %0, %1;" : "=r"(u) : "f"(x));
    return __uint_as_float(u);
}

// mma.sync m16n8k8 tf32: D(16x8 f32) += A(16x8) * B(8x8)
__device__ __forceinline__ void mma_tf32(float* d, const uint32_t* a,
                                         const uint32_t* b) {
    asm volatile(
        "mma.sync.aligned.m16n8k8.row.col.f32.tf32.tf32.f32 "
        "{%0,%1,%2,%3}, {%4,%5,%6,%7}, {%8,%9}, {%0,%1,%2,%3};"
        : "+f"(d[0]), "+f"(d[1]), "+f"(d[2]), "+f"(d[3])
        : "r"(a[0]), "r"(a[1]), "r"(a[2]), "r"(a[3]), "r"(b[0]), "r"(b[1]));
}

// ---------------------------------------------------------------------------
// Fused elementwise tf32 rounding: y=0 -> x, y in 1..4 -> weights.
// ---------------------------------------------------------------------------
__global__ void round_all(const float* __restrict__ x,
                          const float* __restrict__ wq,
                          const float* __restrict__ wk,
                          const float* __restrict__ wv,
                          const float* __restrict__ wo,
                          float* __restrict__ xr, float* __restrict__ wr) {
    const int y = blockIdx.y;
    const float* src;
    float* dst;
    int n4;
    const int CC = kC * kC;
    if (y == 0) { src = x;  dst = xr;           n4 = kT * kC / 4; }
    else if (y == 1) { src = wq; dst = wr;          n4 = CC / 4; }
    else if (y == 2) { src = wk; dst = wr + CC;     n4 = CC / 4; }
    else if (y == 3) { src = wv; dst = wr + 2 * CC; n4 = CC / 4; }
    else             { src = wo; dst = wr + 3 * CC; n4 = CC / 4; }
    int i = blockIdx.x * blockDim.x + threadIdx.x;
    if (i < n4) {
        float4 v = ((const float4*)src)[i];
        v.x = round_tf32(v.x); v.y = round_tf32(v.y);
        v.z = round_tf32(v.z); v.w = round_tf32(v.w);
        ((float4*)dst)[i] = v;
    }
}

// ---------------------------------------------------------------------------
// TF32 tensor-core GEMM: C[m,n] = sum_k A[m,k] * B[n,k]
// CTA tile 128x256x32 (bigger N-tile halves L2 traffic: A refetched 8x not
// 16x). 512 threads / 16 warps, warp tile 32x64 (grid 4x4). 3-stage cp.async
// pipeline, XOR-swizzled smem. blockIdx.z selects (B, C); roundMask bit z
// rounds the output.
// ---------------------------------------------------------------------------
constexpr int GLD = 32;
constexpr int GSTAGE_FLOATS = (128 + 256) * GLD;          // 12288 floats = 48KB
constexpr int GEMM_SMEM_BYTES = 3 * GSTAGE_FLOATS * 4;    // 147456

__device__ __forceinline__ int swoff(int r, int c) {
    return r * GLD + ((((c >> 2) ^ (r & 7)) << 2) | (c & 3));
}

__global__ __launch_bounds__(512, 1) void gemm_tc3(
    const float* __restrict__ A,
    const float* __restrict__ B0, const float* __restrict__ B1,
    const float* __restrict__ B2,
    float* __restrict__ C0, float* __restrict__ C1, float* __restrict__ C2,
    int M, int N, int K, unsigned roundMask) {
    const float* B = (blockIdx.z == 0) ? B0 : (blockIdx.z == 1) ? B1 : B2;
    float* C = (blockIdx.z == 0) ? C0 : (blockIdx.z == 1) ? C1 : C2;
    const bool doRound = (roundMask >> blockIdx.z) & 1u;

    extern __shared__ float smf[];
    const uint32_t sb = smem_u32(smf);
    const int tid = threadIdx.x;
    const int lane = tid & 31;
    const int wid = tid >> 5;      // 0..15
    const int warp_m = wid & 3;    // rows warp_m*32
    const int warp_n = wid >> 2;   // cols warp_n*64
    const int bm = blockIdx.y * 128;
    const int bn = blockIdx.x * 256;

    const int lrow = tid >> 3;     // 0..63
    const int cc8 = tid & 7;       // chunk 0..7

    float d[2][8][4];
#pragma unroll
    for (int mi = 0; mi < 2; mi++)
#pragma unroll
        for (int ni = 0; ni < 8; ni++)
#pragma unroll
            for (int j = 0; j < 4; j++) d[mi][ni][j] = 0.0f;

    const int nStages = K / 32;

    auto prefetch = [&](int s) {
        const int buf = s % 3;
        const uint32_t ab = sb + buf * GSTAGE_FLOATS * 4;
        const uint32_t bb = ab + 128 * GLD * 4;
        const int k0 = s * 32;
        // A: 128 rows
#pragma unroll
        for (int j = 0; j < 2; j++) {
            const int row = lrow + j * 64;
            const int scc = cc8 ^ (row & 7);
            const uint32_t soff = (uint32_t)(row * GLD + scc * 4) * 4;
            cp_async16(ab + soff, &A[(size_t)(bm + row) * K + k0 + cc8 * 4]);
        }
        // B: 256 rows
#pragma unroll
        for (int j = 0; j < 4; j++) {
            const int row = lrow + j * 64;
            const int scc = cc8 ^ (row & 7);
            const uint32_t soff = (uint32_t)(row * GLD + scc * 4) * 4;
            cp_async16(bb + soff, &B[(size_t)(bn + row) * K + k0 + cc8 * 4]);
        }
        CP_COMMIT();
    };

    prefetch(0);
    prefetch(1);

    const int fr = lane >> 2;
    const int fc = lane & 3;

    for (int s = 0; s < nStages; s++) {
        if (s < nStages - 1) {
            asm volatile("cp.async.wait_group 1;" ::: "memory");
        } else {
            asm volatile("cp.async.wait_group 0;" ::: "memory");
        }
        __syncthreads();
        if (s + 2 < nStages) prefetch(s + 2);

        const int buf = s % 3;
        const uint32_t* As = (const uint32_t*)(smf + buf * GSTAGE_FLOATS);
        const uint32_t* Bs = As + 128 * GLD;

#pragma unroll
        for (int kk = 0; kk < 4; kk++) {
            const int c0 = kk * 8 + fc;
            uint32_t a[2][4];
#pragma unroll
            for (int mi = 0; mi < 2; mi++) {
                const int r0 = warp_m * 32 + mi * 16 + fr;
                a[mi][0] = As[swoff(r0, c0)];
                a[mi][1] = As[swoff(r0 + 8, c0)];
                a[mi][2] = As[swoff(r0, c0 + 4)];
                a[mi][3] = As[swoff(r0 + 8, c0 + 4)];
            }
            uint32_t b[8][2];
#pragma unroll
            for (int ni = 0; ni < 8; ni++) {
                const int n0 = warp_n * 64 + ni * 8 + fr;
                b[ni][0] = Bs[swoff(n0, c0)];
                b[ni][1] = Bs[swoff(n0, c0 + 4)];
            }
#pragma unroll
            for (int mi = 0; mi < 2; mi++)
#pragma unroll
                for (int ni = 0; ni < 8; ni++)
                    mma_tf32(d[mi][ni], a[mi], b[ni]);
        }
    }

#pragma unroll
    for (int mi = 0; mi < 2; mi++) {
        const int row = bm + warp_m * 32 + mi * 16 + fr;
#pragma unroll
        for (int ni = 0; ni < 8; ni++) {
            const int col = bn + warp_n * 64 + ni * 8 + fc * 2;
            float2 v0 = make_float2(d[mi][ni][0], d[mi][ni][1]);
            float2 v1 = make_float2(d[mi][ni][2], d[mi][ni][3]);
            if (doRound) {
                v0.x = round_tf32(v0.x); v0.y = round_tf32(v0.y);
                v1.x = round_tf32(v1.x); v1.y = round_tf32(v1.y);
            }
            *(float2*)&C[(size_t)row * N + col] = v0;
            *(float2*)&C[(size_t)(row + 8) * N + col] = v1;
        }
    }
}

// ---------------------------------------------------------------------------
// RoPE in-place on Q and K laid out [T, H*D].
// Q: rotated, scaled by kScale, tf32-rounded. K: rotated, tf32-rounded.
// ---------------------------------------------------------------------------
__global__ void rope_kernel(float* __restrict__ Q, float* __restrict__ K) {
    const int t = blockIdx.x;
    const float ft = (float)t;
    for (int p = threadIdx.x; p < kH * 64; p += blockDim.x) {
        const int h = p >> 6;
        const int i = p & 63;
        const float inv = __expf(-(float)i * 0.14391157f);
        float s, c;
        sincosf(ft * inv, &s, &c);
        const size_t base = (size_t)t * kC + h * kD;
        {
            float x1 = Q[base + i], x2 = Q[base + 64 + i];
            Q[base + i]      = round_tf32((x1 * c - x2 * s) * kScale);
            Q[base + 64 + i] = round_tf32((x2 * c + x1 * s) * kScale);
        }
        {
            float x1 = K[base + i], x2 = K[base + 64 + i];
            K[base + i]      = round_tf32(x1 * c - x2 * s);
            K[base + 64 + i] = round_tf32(x2 * c + x1 * s);
        }
    }
}

// ---------------------------------------------------------------------------
// Tensor-core block-sparse flash attention (round-7 proven config).
// One CTA per (q-PAIR, head): 128 q rows, 256 threads / 8 warps.
// QK warp tile 32x32 (grid 4x2); PV warp tile 32x64 (4x2).
// Software-pipelined cp.async K/V; heavy CTAs first.
// ---------------------------------------------------------------------------
constexpr int AQLD = 132;   // Q [128][132], K [64][132]
constexpr int AVLD = 136;   // V [64][136]
constexpr int APLD = 68;    // S/P [128][68]
constexpr int ATTN_SMEM_FLOATS =
    128 * AQLD + 64 * AQLD + 64 * AVLD + 128 * APLD + 128;
constexpr int ATTN_SMEM_BYTES = ATTN_SMEM_FLOATS * 4;   // 171,520 B

__global__ __launch_bounds__(256, 1) void attn_tc2(const float* __restrict__ Q,
                                                   const float* __restrict__ K,
                                                   const float* __restrict__ V,
                                                   float* __restrict__ Ctx) {
    extern __shared__ float sm[];
    float* Qs = sm;                         // [128][132]
    float* Ks = Qs + 128 * AQLD;            // [64][132]
    float* Vs = Ks + 64 * AQLD;             // [64][136]
    float* Ps = Vs + 64 * AVLD;             // [128][68]
    float* Cr = Ps + 128 * APLD;            // [128]

    const uint32_t sb = smem_u32(sm);
    const uint32_t QsA = sb;
    const uint32_t KsA = sb + 128 * AQLD * 4;
    const uint32_t VsA = KsA + 64 * AQLD * 4;

    const int qp = (gridDim.x - 1) - blockIdx.x;   // heavy-first
    const int h = blockIdx.y;
    const int q0 = 2 * qp;
    const int q1 = q0 + 1;
    const int tid = threadIdx.x;
    const int lane = tid & 31;
    const int wid = tid >> 5;
    const int wm = wid & 3;
    const int wn = wid >> 2;
    const int fr = lane >> 2;
    const int fc = lane & 3;
    const int srow = tid >> 1;
    const int shalf = tid & 1;

    auto is_allowed = [&](int t) {
        const bool glob = (t < 2) || ((t & 3) == 0);
        const bool a0 = (t <= q0) && (((q0 - t) <= 16) || glob);
        const bool a1 = ((q1 - t) <= 16) || glob;
        return a0 || a1;
    };

    auto issueK = [&](int t) {
#pragma unroll
        for (int j = 0; j < 8; j++) {
            const int idx = tid * 4 + j * 1024;
            const int rr = idx >> 7;
            const int dd = idx & 127;
            cp_async16(KsA + (uint32_t)(rr * AQLD + dd) * 4,
                       &K[(size_t)(t * 64 + rr) * kC + h * kD + dd]);
        }
        CP_COMMIT();
    };
    auto issueV = [&](int t) {
#pragma unroll
        for (int j = 0; j < 8; j++) {
            const int idx = tid * 4 + j * 1024;
            const int rr = idx >> 7;
            const int dd = idx & 127;
            cp_async16(VsA + (uint32_t)(rr * AVLD + dd) * 4,
                       &V[(size_t)(t * 64 + rr) * kC + h * kD + dd]);
        }
        CP_COMMIT();
    };

    // Q tile (group 0), then K0 (group 1), V0 (group 2)
#pragma unroll
    for (int j = 0; j < 16; j++) {
        const int idx = tid * 4 + j * 1024;
        const int rr = idx >> 7;
        const int dd = idx & 127;
        cp_async16(QsA + (uint32_t)(rr * AQLD + dd) * 4,
                   &Q[(size_t)(qp * 128 + rr) * kC + h * kD + dd]);
    }
    CP_COMMIT();
    int kb = 0;
    issueK(kb);
    issueV(kb);

    float m = -INFINITY, l = 0.0f;
    float o[2][8][4];
#pragma unroll
    for (int mi = 0; mi < 2; mi++)
#pragma unroll
        for (int ni = 0; ni < 8; ni++)
#pragma unroll
            for (int j = 0; j < 4; j++) o[mi][ni][j] = 0.0f;

    const uint32_t* Qsu = (const uint32_t*)Qs;
    const uint32_t* Ksu = (const uint32_t*)Ks;
    const uint32_t* Vsu = (const uint32_t*)Vs;
    const uint32_t* Psu = (const uint32_t*)Ps;

    while (true) {
        int kbn = kb;
        for (int t = kb + 1; t <= q1; t++) {
            if (is_allowed(t)) { kbn = t; break; }
        }
        const bool glob = (kb < 2) || ((kb & 3) == 0);
        const bool allowed0 = (kb <= q0) && (((q0 - kb) <= 16) || glob);
        const bool allowed1 = ((q1 - kb) <= 16) || glob;

        // wait for K(kb) (Q on first iter too); V(kb) may still be in flight
        asm volatile("cp.async.wait_group 1;" ::: "memory");
        __syncthreads();

        // ---- S = Q @ K^T (128x64) : warp tile 32x32 ----
        float s[2][4][4];
#pragma unroll
        for (int mi = 0; mi < 2; mi++)
#pragma unroll
            for (int ni = 0; ni < 4; ni++)
#pragma unroll
                for (int j = 0; j < 4; j++) s[mi][ni][j] = 0.0f;

#pragma unroll
        for (int kk = 0; kk < 16; kk++) {
            const int c0 = kk * 8 + fc;
            uint32_t a[2][4];
#pragma unroll
            for (int mi = 0; mi < 2; mi++) {
                const int r0 = wm * 32 + mi * 16 + fr;
                a[mi][0] = Qsu[r0 * AQLD + c0];
                a[mi][1] = Qsu[(r0 + 8) * AQLD + c0];
                a[mi][2] = Qsu[r0 * AQLD + c0 + 4];
                a[mi][3] = Qsu[(r0 + 8) * AQLD + c0 + 4];
            }
            uint32_t b[4][2];
#pragma unroll
            for (int ni = 0; ni < 4; ni++) {
                const int n0 = wn * 32 + ni * 8 + fr;
                b[ni][0] = Ksu[n0 * AQLD + c0];
                b[ni][1] = Ksu[n0 * AQLD + c0 + 4];
            }
#pragma unroll
            for (int mi = 0; mi < 2; mi++)
#pragma unroll
                for (int ni = 0; ni < 4; ni++)
                    mma_tf32(s[mi][ni], a[mi], b[ni]);
        }

        // Store S fragments
#pragma unroll
        for (int mi = 0; mi < 2; mi++) {
            const int r = wm * 32 + mi * 16 + fr;
#pragma unroll
            for (int ni = 0; ni < 4; ni++) {
                const int c = wn * 32 + ni * 8 + fc * 2;
                *(float2*)&Ps[r * APLD + c] = make_float2(s[mi][ni][0], s[mi][ni][1]);
                *(float2*)&Ps[(r + 8) * APLD + c] = make_float2(s[mi][ni][2], s[mi][ni][3]);
            }
        }
        __syncthreads();   // all QK reads of Ks done; S visible

        // prefetch next K (overlaps softmax+PV)
        issueK(kbn);

        // ---- scalar online softmax (row srow, cols shalf*32..+31) ----
        {
            const bool rowAllowed = (srow < 64) ? allowed0 : allowed1;
            float* prow = &Ps[srow * APLD + shalf * 32];
            if (rowAllowed) {
                float4 sv[8];
#pragma unroll
                for (int j = 0; j < 8; j++) sv[j] = *(const float4*)&prow[j * 4];
                float lm = -INFINITY;
#pragma unroll
                for (int j = 0; j < 8; j++)
                    lm = fmaxf(lm, fmaxf(fmaxf(sv[j].x, sv[j].y), fmaxf(sv[j].z, sv[j].w)));
                lm = fmaxf(lm, __shfl_xor_sync(0xFFFFFFFFu, lm, 1));
                const float mnew = fmaxf(m, lm);
                const float corr = __expf(m - mnew);
                float rs = 0.0f;
#pragma unroll
                for (int j = 0; j < 8; j++) {
                    sv[j].x = round_tf32(__expf(sv[j].x - mnew));
                    sv[j].y = round_tf32(__expf(sv[j].y - mnew));
                    sv[j].z = round_tf32(__expf(sv[j].z - mnew));
                    sv[j].w = round_tf32(__expf(sv[j].w - mnew));
                    rs += (sv[j].x + sv[j].y) + (sv[j].z + sv[j].w);
                    *(float4*)&prow[j * 4] = sv[j];
                }
                rs += __shfl_xor_sync(0xFFFFFFFFu, rs, 1);
                l = l * corr + rs;
                m = mnew;
                if (shalf == 0) Cr[srow] = corr;
            } else {
                const float4 z = make_float4(0.f, 0.f, 0.f, 0.f);
#pragma unroll
                for (int j = 0; j < 8; j++) *(float4*)&prow[j * 4] = z;
                if (shalf == 0) Cr[srow] = 1.0f;
            }
        }

        // wait for V(kb) (K(kbn) stays in flight), then publish P/Cr/V
        asm volatile("cp.async.wait_group 1;" ::: "memory");
        __syncthreads();

        // ---- O = O*corr + P @ V (128x128) : warp tile 32x64 ----
#pragma unroll
        for (int mi = 0; mi < 2; mi++) {
            const float c0r = Cr[wm * 32 + mi * 16 + fr];
            const float c1r = Cr[wm * 32 + mi * 16 + 8 + fr];
#pragma unroll
            for (int ni = 0; ni < 8; ni++) {
                o[mi][ni][0] *= c0r; o[mi][ni][1] *= c0r;
                o[mi][ni][2] *= c1r; o[mi][ni][3] *= c1r;
            }
        }
#pragma unroll
        for (int kk = 0; kk < 8; kk++) {
            const int c0 = kk * 8 + fc;
            uint32_t a[2][4];
#pragma unroll
            for (int mi = 0; mi < 2; mi++) {
                const int r0 = wm * 32 + mi * 16 + fr;
                a[mi][0] = Psu[r0 * APLD + c0];
                a[mi][1] = Psu[(r0 + 8) * APLD + c0];
                a[mi][2] = Psu[r0 * APLD + c0 + 4];
                a[mi][3] = Psu[(r0 + 8) * APLD + c0 + 4];
            }
            uint32_t b[8][2];
#pragma unroll
            for (int ni = 0; ni < 8; ni++) {
                const int n0 = wn * 64 + ni * 8 + fr;
                b[ni][0] = Vsu[c0 * AVLD + n0];
                b[ni][1] = Vsu[(c0 + 4) * AVLD + n0];
            }
#pragma unroll
            for (int mi = 0; mi < 2; mi++)
#pragma unroll
                for (int ni = 0; ni < 8; ni++)
                    mma_tf32(o[mi][ni], a[mi], b[ni]);
        }
        __syncthreads();   // PV reads of Vs/Ps done

        // prefetch next V (overlaps next tile's QK+softmax)
        issueV(kbn);

        if (kbn == kb) break;
        kb = kbn;
    }

    // Drain, publish 1/l, store
    asm volatile("cp.async.wait_group 0;" ::: "memory");
    __syncthreads();
    if (shalf == 0) Cr[srow] = 1.0f / l;
    __syncthreads();
#pragma unroll
    for (int mi = 0; mi < 2; mi++) {
        const float inv0 = Cr[wm * 32 + mi * 16 + fr];
        const float inv1 = Cr[wm * 32 + mi * 16 + 8 + fr];
        const int row0 = qp * 128 + wm * 32 + mi * 16 + fr;
#pragma unroll
        for (int ni = 0; ni < 8; ni++) {
            const int col = h * kD + wn * 64 + ni * 8 + fc * 2;
            *(float2*)&Ctx[(size_t)row0 * kC + col] =
                make_float2(round_tf32(o[mi][ni][0] * inv0),
                            round_tf32(o[mi][ni][1] * inv0));
            *(float2*)&Ctx[(size_t)(row0 + 8) * kC + col] =
                make_float2(round_tf32(o[mi][ni][2] * inv1),
                            round_tf32(o[mi][ni][3] * inv1));
        }
    }
}

// ---------------------------------------------------------------------------
extern "C" void kernel_launch(void* const* d_in, const int* in_sizes, int n_in,
                              void* d_out, int out_size) {
    const float* x  = (const float*)d_in[0];
    const float* wq = (const float*)d_in[1];
    const float* wk = (const float*)d_in[2];
    const float* wv = (const float*)d_in[3];
    const float* wo = (const float*)d_in[4];
    float* out = (float*)d_out;

    float *qp, *kp, *vp, *cp, *xr, *wr;
    cudaGetSymbolAddress((void**)&qp, g_q);
    cudaGetSymbolAddress((void**)&kp, g_k);
    cudaGetSymbolAddress((void**)&vp, g_v);
    cudaGetSymbolAddress((void**)&cp, g_ctx);
    cudaGetSymbolAddress((void**)&xr, g_xr);
    cudaGetSymbolAddress((void**)&wr, g_wr);

    cudaFuncSetAttribute(gemm_tc3, cudaFuncAttributeMaxDynamicSharedMemorySize,
                         GEMM_SMEM_BYTES);
    cudaFuncSetAttribute(attn_tc2, cudaFuncAttributeMaxDynamicSharedMemorySize,
                         ATTN_SMEM_BYTES);

    const int CC = kC * kC;

    round_all<<<dim3(kT * kC / 4 / 256, 5), 256>>>(x, wq, wk, wv, wo, xr, wr);

    // Fused QKV projection; V output tf32-rounded in epilogue (mask bit 2)
    gemm_tc3<<<dim3(kC / 256, kT / 128, 3), 512, GEMM_SMEM_BYTES>>>(
        xr, wr + 0 * CC, wr + 1 * CC, wr + 2 * CC, qp, kp, vp, kT, kC, kC, 4u);

    rope_kernel<<<kT, 256>>>(qp, kp);

    attn_tc2<<<dim3(kT / 128, kH), 256, ATTN_SMEM_BYTES>>>(qp, kp, vp, cp);

    // Output projection (no rounding)
    gemm_tc3<<<dim3(kC / 256, kT / 128, 1), 512, GEMM_SMEM_BYTES>>>(
        cp, wr + 3 * CC, wr + 3 * CC, wr + 3 * CC, out, out, out, kT, kC, kC, 0u);
}

// round 11
// speedup vs baseline: 1.0670x; 1.0670x over previous
#include <cuda_runtime.h>
#include <math.h>
#include <stdint.h>

// Problem constants
constexpr int kT = 4096;
constexpr int kC = 2048;
constexpr int kH = 16;
constexpr int kD = 128;
constexpr float kScale = 0.08838834764831845f;

// Scratch (device globals — no cudaMalloc allowed)
__device__ float g_q[kT * kC];
__device__ float g_k[kT * kC];
__device__ float g_v[kT * kC];
__device__ float g_ctx[kT * kC];
__device__ float g_xr[kT * kC];          // tf32-rounded x
__device__ float g_wr[4 * kC * kC];      // tf32-rounded wq,wk,wv,wo

// ---------------------------------------------------------------------------
__device__ __forceinline__ uint32_t smem_u32(const void* p) {
    uint32_t a;
    asm("{ .reg .u64 t; cvta.to.shared.u64 t, %1; cvt.u32.u64 %0, t; }"
        : "=r"(a) : "l"(p));
    return a;
}

__device__ __forceinline__ void cp_async16(uint32_t saddr, const void* gaddr) {
    asm volatile("cp.async.cg.shared.global [%0], [%1], 16;"
                 :: "r"(saddr), "l"(gaddr));
}
#define CP_COMMIT() asm volatile("cp.async.commit_group;" ::: "memory")

__device__ __forceinline__ float round_tf32(float x) {
    uint32_t u;
    asm("cvt.rna.tf32.f32 %0, %1;" : "=r"(u) : "f"(x));
    return __uint_as_float(u);
}

// mma.sync m16n8k8 tf32: D(16x8 f32) += A(16x8) * B(8x8)
__device__ __forceinline__ void mma_tf32(float* d, const uint32_t* a,
                                         const uint32_t* b) {
    asm volatile(
        "mma.sync.aligned.m16n8k8.row.col.f32.tf32.tf32.f32 "
        "{%0,%1,%2,%3}, {%4,%5,%6,%7}, {%8,%9}, {%0,%1,%2,%3};"
        : "+f"(d[0]), "+f"(d[1]), "+f"(d[2]), "+f"(d[3])
        : "r"(a[0]), "r"(a[1]), "r"(a[2]), "r"(a[3]), "r"(b[0]), "r"(b[1]));
}

// ---------------------------------------------------------------------------
// Fused elementwise tf32 rounding: y=0 -> x, y in 1..4 -> weights.
// ---------------------------------------------------------------------------
__global__ void round_all(const float* __restrict__ x,
                          const float* __restrict__ wq,
                          const float* __restrict__ wk,
                          const float* __restrict__ wv,
                          const float* __restrict__ wo,
                          float* __restrict__ xr, float* __restrict__ wr) {
    const int y = blockIdx.y;
    const float* src;
    float* dst;
    int n4;
    const int CC = kC * kC;
    if (y == 0) { src = x;  dst = xr;           n4 = kT * kC / 4; }
    else if (y == 1) { src = wq; dst = wr;          n4 = CC / 4; }
    else if (y == 2) { src = wk; dst = wr + CC;     n4 = CC / 4; }
    else if (y == 3) { src = wv; dst = wr + 2 * CC; n4 = CC / 4; }
    else             { src = wo; dst = wr + 3 * CC; n4 = CC / 4; }
    int i = blockIdx.x * blockDim.x + threadIdx.x;
    if (i < n4) {
        float4 v = ((const float4*)src)[i];
        v.x = round_tf32(v.x); v.y = round_tf32(v.y);
        v.z = round_tf32(v.z); v.w = round_tf32(v.w);
        ((float4*)dst)[i] = v;
    }
}

// ---------------------------------------------------------------------------
// TF32 tensor-core GEMM (R9 config — measured at the legacy-HMMA ceiling):
// C[m,n] = sum_k A[m,k] * B[n,k]. CTA tile 128x128x32, 4 warps, warp tile
// 64x64, 3-stage cp.async, XOR-swizzled smem, occ 2.
// ---------------------------------------------------------------------------
constexpr int GLD = 32;
constexpr int GSTAGE_FLOATS = 2 * 128 * GLD;
constexpr int GEMM_SMEM_BYTES = 3 * GSTAGE_FLOATS * 4;  // 98304

__device__ __forceinline__ int swoff(int r, int c) {
    return r * GLD + ((((c >> 2) ^ (r & 7)) << 2) | (c & 3));
}

__global__ __launch_bounds__(128, 2) void gemm_tc3(
    const float* __restrict__ A,
    const float* __restrict__ B0, const float* __restrict__ B1,
    const float* __restrict__ B2,
    float* __restrict__ C0, float* __restrict__ C1, float* __restrict__ C2,
    int M, int N, int K, unsigned roundMask) {
    const float* B = (blockIdx.z == 0) ? B0 : (blockIdx.z == 1) ? B1 : B2;
    float* C = (blockIdx.z == 0) ? C0 : (blockIdx.z == 1) ? C1 : C2;
    const bool doRound = (roundMask >> blockIdx.z) & 1u;

    extern __shared__ float smf[];
    const uint32_t sb = smem_u32(smf);
    const int tid = threadIdx.x;
    const int lane = tid & 31;
    const int wid = tid >> 5;      // 0..3
    const int warp_m = wid & 1;    // rows warp_m*64
    const int warp_n = wid >> 1;   // cols warp_n*64
    const int bm = blockIdx.y * 128;
    const int bn = blockIdx.x * 128;

    const int lrow = tid >> 3;     // 0..15 (+j*16 -> 0..127)
    const int cc8 = tid & 7;       // chunk 0..7

    float d[4][8][4];
#pragma unroll
    for (int mi = 0; mi < 4; mi++)
#pragma unroll
        for (int ni = 0; ni < 8; ni++)
#pragma unroll
            for (int j = 0; j < 4; j++) d[mi][ni][j] = 0.0f;

    const int nStages = K / 32;

    auto prefetch = [&](int s) {
        const int buf = s % 3;
        const uint32_t ab = sb + buf * GSTAGE_FLOATS * 4;
        const uint32_t bb = ab + 128 * GLD * 4;
        const int k0 = s * 32;
#pragma unroll
        for (int j = 0; j < 8; j++) {
            const int row = lrow + j * 16;
            const int scc = cc8 ^ (row & 7);
            const uint32_t soff = (uint32_t)(row * GLD + scc * 4) * 4;
            cp_async16(ab + soff, &A[(size_t)(bm + row) * K + k0 + cc8 * 4]);
            cp_async16(bb + soff, &B[(size_t)(bn + row) * K + k0 + cc8 * 4]);
        }
        CP_COMMIT();
    };

    prefetch(0);
    prefetch(1);

    const int fr = lane >> 2;
    const int fc = lane & 3;

    for (int s = 0; s < nStages; s++) {
        if (s < nStages - 1) {
            asm volatile("cp.async.wait_group 1;" ::: "memory");
        } else {
            asm volatile("cp.async.wait_group 0;" ::: "memory");
        }
        __syncthreads();
        if (s + 2 < nStages) prefetch(s + 2);

        const int buf = s % 3;
        const uint32_t* As = (const uint32_t*)(smf + buf * GSTAGE_FLOATS);
        const uint32_t* Bs = As + 128 * GLD;

#pragma unroll
        for (int kk = 0; kk < 4; kk++) {
            const int c0 = kk * 8 + fc;
            uint32_t a[4][4];
#pragma unroll
            for (int mi = 0; mi < 4; mi++) {
                const int r0 = warp_m * 64 + mi * 16 + fr;
                a[mi][0] = As[swoff(r0, c0)];
                a[mi][1] = As[swoff(r0 + 8, c0)];
                a[mi][2] = As[swoff(r0, c0 + 4)];
                a[mi][3] = As[swoff(r0 + 8, c0 + 4)];
            }
            uint32_t b[8][2];
#pragma unroll
            for (int ni = 0; ni < 8; ni++) {
                const int n0 = warp_n * 64 + ni * 8 + fr;
                b[ni][0] = Bs[swoff(n0, c0)];
                b[ni][1] = Bs[swoff(n0, c0 + 4)];
            }
#pragma unroll
            for (int mi = 0; mi < 4; mi++)
#pragma unroll
                for (int ni = 0; ni < 8; ni++)
                    mma_tf32(d[mi][ni], a[mi], b[ni]);
        }
    }

#pragma unroll
    for (int mi = 0; mi < 4; mi++) {
        const int row = bm + warp_m * 64 + mi * 16 + fr;
#pragma unroll
        for (int ni = 0; ni < 8; ni++) {
            const int col = bn + warp_n * 64 + ni * 8 + fc * 2;
            float2 v0 = make_float2(d[mi][ni][0], d[mi][ni][1]);
            float2 v1 = make_float2(d[mi][ni][2], d[mi][ni][3]);
            if (doRound) {
                v0.x = round_tf32(v0.x); v0.y = round_tf32(v0.y);
                v1.x = round_tf32(v1.x); v1.y = round_tf32(v1.y);
            }
            *(float2*)&C[(size_t)row * N + col] = v0;
            *(float2*)&C[(size_t)(row + 8) * N + col] = v1;
        }
    }
}

// ---------------------------------------------------------------------------
// RoPE in-place on Q and K laid out [T, H*D].
// Q: rotated, scaled by kScale, tf32-rounded. K: rotated, tf32-rounded.
// ---------------------------------------------------------------------------
__global__ void rope_kernel(float* __restrict__ Q, float* __restrict__ K) {
    const int t = blockIdx.x;
    const float ft = (float)t;
    for (int p = threadIdx.x; p < kH * 64; p += blockDim.x) {
        const int h = p >> 6;
        const int i = p & 63;
        const float inv = __expf(-(float)i * 0.14391157f);
        float s, c;
        sincosf(ft * inv, &s, &c);
        const size_t base = (size_t)t * kC + h * kD;
        {
            float x1 = Q[base + i], x2 = Q[base + 64 + i];
            Q[base + i]      = round_tf32((x1 * c - x2 * s) * kScale);
            Q[base + 64 + i] = round_tf32((x2 * c + x1 * s) * kScale);
        }
        {
            float x1 = K[base + i], x2 = K[base + 64 + i];
            K[base + i]      = round_tf32(x1 * c - x2 * s);
            K[base + 64 + i] = round_tf32(x2 * c + x1 * s);
        }
    }
}

// ---------------------------------------------------------------------------
// Tensor-core block-sparse flash attention, 2-CTA/SM variant.
// One CTA per (q-block, head): 64 q rows, 128 threads / 4 warps.
// Same proven warp tiles as R7: QK 32x32 (grid 2x2), PV 32x64 (2x2).
// K and V SHARE one smem buffer (K at LD132 during QK, V at LD136 during PV
// — each orientation conflict-free). smem 86 KB -> 2 CTAs/SM: two
// independent barrier domains hide each other's stalls.
// allowed(qb,kb) = kb <= qb && (qb-kb <= 16 || kb < 2 || (kb & 3) == 0)
// — uniform across the whole 64-row tile, so no row masking at all.
// ---------------------------------------------------------------------------
constexpr int AQLD = 132;   // Q [64][132]
constexpr int AKLD = 132;   // K layout in shared KV buffer
constexpr int AVLD = 136;   // V layout in shared KV buffer
constexpr int APLD = 68;    // S/P [64][68]
constexpr int AKV_FLOATS = 64 * AVLD;               // 8704 (max of K/V)
constexpr int ATTN_SMEM_FLOATS =
    64 * AQLD + AKV_FLOATS + 64 * APLD + 64;        // 21568
constexpr int ATTN_SMEM_BYTES = ATTN_SMEM_FLOATS * 4;   // 86,272 B

__global__ __launch_bounds__(128, 2) void attn_tc3(const float* __restrict__ Q,
                                                   const float* __restrict__ K,
                                                   const float* __restrict__ V,
                                                   float* __restrict__ Ctx) {
    extern __shared__ float sm[];
    float* Qs = sm;                          // [64][132]
    float* KV = Qs + 64 * AQLD;              // K:[64][132] / V:[64][136]
    float* Ps = KV + AKV_FLOATS;             // [64][68]
    float* Cr = Ps + 64 * APLD;              // [64]

    const uint32_t sb = smem_u32(sm);
    const uint32_t QsA = sb;
    const uint32_t KVA = sb + 64 * AQLD * 4;

    const int qb = (gridDim.x - 1) - blockIdx.x;   // heavy-first
    const int h = blockIdx.y;
    const int tid = threadIdx.x;
    const int lane = tid & 31;
    const int wid = tid >> 5;      // 0..3
    const int wm = wid & 1;        // rows wm*32
    const int wn = wid >> 1;       // QK cols wn*32 ; PV dims wn*64
    const int fr = lane >> 2;
    const int fc = lane & 3;
    const int srow = tid >> 1;     // softmax row 0..63
    const int shalf = tid & 1;     // softmax col half (32 cols)

    auto is_allowed = [&](int t) {
        return (t <= qb) && (((qb - t) <= 16) || (t < 2) || ((t & 3) == 0));
    };

    auto issueK = [&](int t) {
#pragma unroll
        for (int j = 0; j < 16; j++) {
            const int idx = tid * 4 + j * 512;
            const int rr = idx >> 7;
            const int dd = idx & 127;
            cp_async16(KVA + (uint32_t)(rr * AKLD + dd) * 4,
                       &K[(size_t)(t * 64 + rr) * kC + h * kD + dd]);
        }
        CP_COMMIT();
    };
    auto issueV = [&](int t) {
#pragma unroll
        for (int j = 0; j < 16; j++) {
            const int idx = tid * 4 + j * 512;
            const int rr = idx >> 7;
            const int dd = idx & 127;
            cp_async16(KVA + (uint32_t)(rr * AVLD + dd) * 4,
                       &V[(size_t)(t * 64 + rr) * kC + h * kD + dd]);
        }
        CP_COMMIT();
    };

    // Prologue: Q tile + K(0)  (kb=0 always allowed)
#pragma unroll
    for (int j = 0; j < 16; j++) {
        const int idx = tid * 4 + j * 512;
        const int rr = idx >> 7;
        const int dd = idx & 127;
        cp_async16(QsA + (uint32_t)(rr * AQLD + dd) * 4,
                   &Q[(size_t)(qb * 64 + rr) * kC + h * kD + dd]);
    }
    CP_COMMIT();
    int kb = 0;
    issueK(kb);
    asm volatile("cp.async.wait_group 0;" ::: "memory");
    __syncthreads();

    float m = -INFINITY, l = 0.0f;
    float o[2][8][4];
#pragma unroll
    for (int mi = 0; mi < 2; mi++)
#pragma unroll
        for (int ni = 0; ni < 8; ni++)
#pragma unroll
            for (int j = 0; j < 4; j++) o[mi][ni][j] = 0.0f;

    const uint32_t* Qsu = (const uint32_t*)Qs;
    const uint32_t* KVu = (const uint32_t*)KV;
    const uint32_t* Psu = (const uint32_t*)Ps;

    while (true) {
        int kbn = kb;
        for (int t = kb + 1; t <= qb; t++) {
            if (is_allowed(t)) { kbn = t; break; }
        }

        // ---- S = Q @ K^T (64x64) : warp tile 32x32 ----
        float s[2][4][4];
#pragma unroll
        for (int mi = 0; mi < 2; mi++)
#pragma unroll
            for (int ni = 0; ni < 4; ni++)
#pragma unroll
                for (int j = 0; j < 4; j++) s[mi][ni][j] = 0.0f;

#pragma unroll
        for (int kk = 0; kk < 16; kk++) {
            const int c0 = kk * 8 + fc;
            uint32_t a[2][4];
#pragma unroll
            for (int mi = 0; mi < 2; mi++) {
                const int r0 = wm * 32 + mi * 16 + fr;
                a[mi][0] = Qsu[r0 * AQLD + c0];
                a[mi][1] = Qsu[(r0 + 8) * AQLD + c0];
                a[mi][2] = Qsu[r0 * AQLD + c0 + 4];
                a[mi][3] = Qsu[(r0 + 8) * AQLD + c0 + 4];
            }
            uint32_t b[4][2];
#pragma unroll
            for (int ni = 0; ni < 4; ni++) {
                const int n0 = wn * 32 + ni * 8 + fr;
                b[ni][0] = KVu[n0 * AKLD + c0];
                b[ni][1] = KVu[n0 * AKLD + c0 + 4];
            }
#pragma unroll
            for (int mi = 0; mi < 2; mi++)
#pragma unroll
                for (int ni = 0; ni < 4; ni++)
                    mma_tf32(s[mi][ni], a[mi], b[ni]);
        }

        // Store S fragments
#pragma unroll
        for (int mi = 0; mi < 2; mi++) {
            const int r = wm * 32 + mi * 16 + fr;
#pragma unroll
            for (int ni = 0; ni < 4; ni++) {
                const int c = wn * 32 + ni * 8 + fc * 2;
                *(float2*)&Ps[r * APLD + c] = make_float2(s[mi][ni][0], s[mi][ni][1]);
                *(float2*)&Ps[(r + 8) * APLD + c] = make_float2(s[mi][ni][2], s[mi][ni][3]);
            }
        }
        __syncthreads();   // K reads + S writes complete -> KV buffer free

        // V overwrites K's buffer; lands during softmax
        issueV(kb);

        // ---- scalar online softmax (row srow, cols shalf*32..+31) ----
        {
            float* prow = &Ps[srow * APLD + shalf * 32];
            float4 sv[8];
#pragma unroll
            for (int j = 0; j < 8; j++) sv[j] = *(const float4*)&prow[j * 4];
            float lm = -INFINITY;
#pragma unroll
            for (int j = 0; j < 8; j++)
                lm = fmaxf(lm, fmaxf(fmaxf(sv[j].x, sv[j].y), fmaxf(sv[j].z, sv[j].w)));
            lm = fmaxf(lm, __shfl_xor_sync(0xFFFFFFFFu, lm, 1));
            const float mnew = fmaxf(m, lm);
            const float corr = __expf(m - mnew);
            float rs = 0.0f;
#pragma unroll
            for (int j = 0; j < 8; j++) {
                sv[j].x = round_tf32(__expf(sv[j].x - mnew));
                sv[j].y = round_tf32(__expf(sv[j].y - mnew));
                sv[j].z = round_tf32(__expf(sv[j].z - mnew));
                sv[j].w = round_tf32(__expf(sv[j].w - mnew));
                rs += (sv[j].x + sv[j].y) + (sv[j].z + sv[j].w);
                *(float4*)&prow[j * 4] = sv[j];
            }
            rs += __shfl_xor_sync(0xFFFFFFFFu, rs, 1);
            l = l * corr + rs;
            m = mnew;
            if (shalf == 0) Cr[srow] = corr;
        }

        asm volatile("cp.async.wait_group 0;" ::: "memory");
        __syncthreads();   // V, P, Cr ready

        // ---- O = O*corr + P @ V (64x128) : warp tile 32x64 ----
#pragma unroll
        for (int mi = 0; mi < 2; mi++) {
            const float c0r = Cr[wm * 32 + mi * 16 + fr];
            const float c1r = Cr[wm * 32 + mi * 16 + 8 + fr];
#pragma unroll
            for (int ni = 0; ni < 8; ni++) {
                o[mi][ni][0] *= c0r; o[mi][ni][1] *= c0r;
                o[mi][ni][2] *= c1r; o[mi][ni][3] *= c1r;
            }
        }
#pragma unroll
        for (int kk = 0; kk < 8; kk++) {
            const int c0 = kk * 8 + fc;
            uint32_t a[2][4];
#pragma unroll
            for (int mi = 0; mi < 2; mi++) {
                const int r0 = wm * 32 + mi * 16 + fr;
                a[mi][0] = Psu[r0 * APLD + c0];
                a[mi][1] = Psu[(r0 + 8) * APLD + c0];
                a[mi][2] = Psu[r0 * APLD + c0 + 4];
                a[mi][3] = Psu[(r0 + 8) * APLD + c0 + 4];
            }
            uint32_t b[8][2];
#pragma unroll
            for (int ni = 0; ni < 8; ni++) {
                const int n0 = wn * 64 + ni * 8 + fr;
                b[ni][0] = KVu[c0 * AVLD + n0];
                b[ni][1] = KVu[(c0 + 4) * AVLD + n0];
            }
#pragma unroll
            for (int mi = 0; mi < 2; mi++)
#pragma unroll
                for (int ni = 0; ni < 8; ni++)
                    mma_tf32(o[mi][ni], a[mi], b[ni]);
        }
        __syncthreads();   // V/P reads complete -> KV buffer free

        if (kbn == kb) break;
        issueK(kbn);
        kb = kbn;
        asm volatile("cp.async.wait_group 0;" ::: "memory");
        __syncthreads();   // K ready
    }

    // Publish 1/l, normalize + round + store
    if (shalf == 0) Cr[srow] = 1.0f / l;
    __syncthreads();
#pragma unroll
    for (int mi = 0; mi < 2; mi++) {
        const float inv0 = Cr[wm * 32 + mi * 16 + fr];
        const float inv1 = Cr[wm * 32 + mi * 16 + 8 + fr];
        const int row0 = qb * 64 + wm * 32 + mi * 16 + fr;
#pragma unroll
        for (int ni = 0; ni < 8; ni++) {
            const int col = h * kD + wn * 64 + ni * 8 + fc * 2;
            *(float2*)&Ctx[(size_t)row0 * kC + col] =
                make_float2(round_tf32(o[mi][ni][0] * inv0),
                            round_tf32(o[mi][ni][1] * inv0));
            *(float2*)&Ctx[(size_t)(row0 + 8) * kC + col] =
                make_float2(round_tf32(o[mi][ni][2] * inv1),
                            round_tf32(o[mi][ni][3] * inv1));
        }
    }
}

// ---------------------------------------------------------------------------
extern "C" void kernel_launch(void* const* d_in, const int* in_sizes, int n_in,
                              void* d_out, int out_size) {
    const float* x  = (const float*)d_in[0];
    const float* wq = (const float*)d_in[1];
    const float* wk = (const float*)d_in[2];
    const float* wv = (const float*)d_in[3];
    const float* wo = (const float*)d_in[4];
    float* out = (float*)d_out;

    float *qp, *kp, *vp, *cp, *xr, *wr;
    cudaGetSymbolAddress((void**)&qp, g_q);
    cudaGetSymbolAddress((void**)&kp, g_k);
    cudaGetSymbolAddress((void**)&vp, g_v);
    cudaGetSymbolAddress((void**)&cp, g_ctx);
    cudaGetSymbolAddress((void**)&xr, g_xr);
    cudaGetSymbolAddress((void**)&wr, g_wr);

    cudaFuncSetAttribute(gemm_tc3, cudaFuncAttributeMaxDynamicSharedMemorySize,
                         GEMM_SMEM_BYTES);
    cudaFuncSetAttribute(attn_tc3, cudaFuncAttributeMaxDynamicSharedMemorySize,
                         ATTN_SMEM_BYTES);

    const int CC = kC * kC;

    round_all<<<dim3(kT * kC / 4 / 256, 5), 256>>>(x, wq, wk, wv, wo, xr, wr);

    // Fused QKV projection; V output tf32-rounded in epilogue (mask bit 2)
    gemm_tc3<<<dim3(kC / 128, kT / 128, 3), 128, GEMM_SMEM_BYTES>>>(
        xr, wr + 0 * CC, wr + 1 * CC, wr + 2 * CC, qp, kp, vp, kT, kC, kC, 4u);

    rope_kernel<<<kT, 256>>>(qp, kp);

    attn_tc3<<<dim3(kT / 64, kH), 128, ATTN_SMEM_BYTES>>>(qp, kp, vp, cp);

    // Output projection (no rounding)
    gemm_tc3<<<dim3(kC / 128, kT / 128, 1), 128, GEMM_SMEM_BYTES>>>(
        cp, wr + 3 * CC, wr + 3 * CC, wr + 3 * CC, out, out, out, kT, kC, kC, 0u);
}

// round 12
// speedup vs baseline: 1.5693x; 1.4708x over previous
#include <cuda_runtime.h>
#include <cuda_fp16.h>
#include <math.h>
#include <stdint.h>

// Problem constants
constexpr int kT = 4096;
constexpr int kC = 2048;
constexpr int kH = 16;
constexpr int kD = 128;
constexpr float kScale = 0.08838834764831845f;

// Scratch (device globals — no cudaMalloc allowed)
__device__ __half g_xh[kT * kC];        // x in fp16
__device__ __half g_wh[4 * kC * kC];    // wq,wk,wv,wo in fp16
__device__ __half g_qh[kT * kC];        // q fp16 (rope'd, scaled)
__device__ __half g_kh[kT * kC];        // k fp16 (rope'd)
__device__ float  g_v [kT * kC];        // v fp32 (tf32-rounded)
__device__ __half g_ch[kT * kC];        // attention output fp16

// ---------------------------------------------------------------------------
__device__ __forceinline__ uint32_t smem_u32(const void* p) {
    uint32_t a;
    asm("{ .reg .u64 t; cvta.to.shared.u64 t, %1; cvt.u32.u64 %0, t; }"
        : "=r"(a) : "l"(p));
    return a;
}

__device__ __forceinline__ void cp_async16(uint32_t saddr, const void* gaddr) {
    asm volatile("cp.async.cg.shared.global [%0], [%1], 16;"
                 :: "r"(saddr), "l"(gaddr));
}
#define CP_COMMIT() asm volatile("cp.async.commit_group;" ::: "memory")

__device__ __forceinline__ float round_tf32(float x) {
    uint32_t u;
    asm("cvt.rna.tf32.f32 %0, %1;" : "=r"(u) : "f"(x));
    return __uint_as_float(u);
}

// mma.sync m16n8k16 fp16: D(16x8 f32) += A(16x16 f16) * B(16x8 f16)
__device__ __forceinline__ void mma_f16(float* d, const uint32_t* a,
                                        const uint32_t* b) {
    asm volatile(
        "mma.sync.aligned.m16n8k16.row.col.f32.f16.f16.f32 "
        "{%0,%1,%2,%3}, {%4,%5,%6,%7}, {%8,%9}, {%0,%1,%2,%3};"
        : "+f"(d[0]), "+f"(d[1]), "+f"(d[2]), "+f"(d[3])
        : "r"(a[0]), "r"(a[1]), "r"(a[2]), "r"(a[3]), "r"(b[0]), "r"(b[1]));
}

// mma.sync m16n8k8 tf32 (kept for attention PV path)
__device__ __forceinline__ void mma_tf32(float* d, const uint32_t* a,
                                         const uint32_t* b) {
    asm volatile(
        "mma.sync.aligned.m16n8k8.row.col.f32.tf32.tf32.f32 "
        "{%0,%1,%2,%3}, {%4,%5,%6,%7}, {%8,%9}, {%0,%1,%2,%3};"
        : "+f"(d[0]), "+f"(d[1]), "+f"(d[2]), "+f"(d[3])
        : "r"(a[0]), "r"(a[1]), "r"(a[2]), "r"(a[3]), "r"(b[0]), "r"(b[1]));
}

// ---------------------------------------------------------------------------
// Fused fp32 -> fp16 conversion: y=0 -> x, y in 1..4 -> weights.
// ---------------------------------------------------------------------------
__global__ void convert_all(const float* __restrict__ x,
                            const float* __restrict__ wq,
                            const float* __restrict__ wk,
                            const float* __restrict__ wv,
                            const float* __restrict__ wo,
                            __half* __restrict__ xh, __half* __restrict__ wh) {
    const int y = blockIdx.y;
    const float* src;
    __half* dst;
    int n4;
    const int CC = kC * kC;
    if (y == 0) { src = x;  dst = xh;           n4 = kT * kC / 4; }
    else if (y == 1) { src = wq; dst = wh;          n4 = CC / 4; }
    else if (y == 2) { src = wk; dst = wh + CC;     n4 = CC / 4; }
    else if (y == 3) { src = wv; dst = wh + 2 * CC; n4 = CC / 4; }
    else             { src = wo; dst = wh + 3 * CC; n4 = CC / 4; }
    int i = blockIdx.x * blockDim.x + threadIdx.x;
    if (i < n4) {
        float4 v = ((const float4*)src)[i];
        __half2 h0 = __floats2half2_rn(v.x, v.y);
        __half2 h1 = __floats2half2_rn(v.z, v.w);
        uint2 u;
        u.x = *(uint32_t*)&h0;
        u.y = *(uint32_t*)&h1;
        *(uint2*)(dst + i * 4) = u;
    }
}

// ---------------------------------------------------------------------------
// FP16 tensor-core GEMM: C[m,n] = sum_k A[m,k] * B[n,k], fp32 accumulate.
// CTA tile 128x128x32, 4 warps, warp tile 64x64, m16n8k16 (half the HMMA
// instructions of the tf32 version). 3-stage cp.async. Smem rows 32 halfs
// padded to 40 (conflict-free fragment loads, no XOR needed).
// blockIdx.z selects (B, C). halfMask bit z: output fp16; roundMask bit z:
// tf32-round fp32 output.
// ---------------------------------------------------------------------------
constexpr int GLDH = 40;                                 // halfs per row
constexpr int GSTAGE_HALFS = 2 * 128 * GLDH;             // 10240 halfs = 20KB
constexpr int GEMM_SMEM_BYTES = 3 * GSTAGE_HALFS * 2;    // 61440

__global__ __launch_bounds__(128, 2) void gemm_h3(
    const __half* __restrict__ A,
    const __half* __restrict__ B0, const __half* __restrict__ B1,
    const __half* __restrict__ B2,
    void* __restrict__ C0, void* __restrict__ C1, void* __restrict__ C2,
    int M, int N, int K, unsigned halfMask, unsigned roundMask) {
    const __half* B = (blockIdx.z == 0) ? B0 : (blockIdx.z == 1) ? B1 : B2;
    void* Cv = (blockIdx.z == 0) ? C0 : (blockIdx.z == 1) ? C1 : C2;
    const bool halfOut = (halfMask >> blockIdx.z) & 1u;
    const bool doRound = (roundMask >> blockIdx.z) & 1u;

    extern __shared__ __half smh[];
    const uint32_t sb = smem_u32(smh);
    const int tid = threadIdx.x;
    const int lane = tid & 31;
    const int wid = tid >> 5;      // 0..3
    const int warp_m = wid & 1;    // rows warp_m*64
    const int warp_n = wid >> 1;   // cols warp_n*64
    const int bm = blockIdx.y * 128;
    const int bn = blockIdx.x * 128;

    float d[4][8][4];
#pragma unroll
    for (int mi = 0; mi < 4; mi++)
#pragma unroll
        for (int ni = 0; ni < 8; ni++)
#pragma unroll
            for (int j = 0; j < 4; j++) d[mi][ni][j] = 0.0f;

    const int nStages = K / 32;

    auto prefetch = [&](int s) {
        const int buf = s % 3;
        const uint32_t ab = sb + buf * GSTAGE_HALFS * 2;
        const uint32_t bb = ab + 128 * GLDH * 2;
        const int k0 = s * 32;
        // each tensor: 128 rows x 64B = 512 chunks of 16B; 4 per thread
#pragma unroll
        for (int j = 0; j < 4; j++) {
            const int idx = tid + j * 128;
            const int row = idx >> 2;
            const int ch = idx & 3;
            const uint32_t soff = (uint32_t)row * 80 + ch * 16;
            cp_async16(ab + soff, &A[(size_t)(bm + row) * K + k0 + ch * 8]);
            cp_async16(bb + soff, &B[(size_t)(bn + row) * K + k0 + ch * 8]);
        }
        CP_COMMIT();
    };

    prefetch(0);
    prefetch(1);

    const int fr = lane >> 2;
    const int fc = lane & 3;

    for (int s = 0; s < nStages; s++) {
        if (s < nStages - 1) {
            asm volatile("cp.async.wait_group 1;" ::: "memory");
        } else {
            asm volatile("cp.async.wait_group 0;" ::: "memory");
        }
        __syncthreads();
        if (s + 2 < nStages) prefetch(s + 2);

        const int buf = s % 3;
        const uint32_t* As = (const uint32_t*)(smh + buf * GSTAGE_HALFS);
        const uint32_t* Bs = As + 128 * (GLDH / 2);   // +128 rows of 20 words

#pragma unroll
        for (int kk = 0; kk < 2; kk++) {
            const int c0 = kk * 8 + fc;
            uint32_t a[4][4];
#pragma unroll
            for (int mi = 0; mi < 4; mi++) {
                const int r0 = warp_m * 64 + mi * 16 + fr;
                a[mi][0] = As[r0 * 20 + c0];
                a[mi][1] = As[(r0 + 8) * 20 + c0];
                a[mi][2] = As[r0 * 20 + c0 + 4];
                a[mi][3] = As[(r0 + 8) * 20 + c0 + 4];
            }
            uint32_t b[8][2];
#pragma unroll
            for (int ni = 0; ni < 8; ni++) {
                const int n0 = warp_n * 64 + ni * 8 + fr;
                b[ni][0] = Bs[n0 * 20 + c0];
                b[ni][1] = Bs[n0 * 20 + c0 + 4];
            }
#pragma unroll
            for (int mi = 0; mi < 4; mi++)
#pragma unroll
                for (int ni = 0; ni < 8; ni++)
                    mma_f16(d[mi][ni], a[mi], b[ni]);
        }
    }

    if (halfOut) {
        __half* C = (__half*)Cv;
#pragma unroll
        for (int mi = 0; mi < 4; mi++) {
            const int row = bm + warp_m * 64 + mi * 16 + fr;
#pragma unroll
            for (int ni = 0; ni < 8; ni++) {
                const int col = bn + warp_n * 64 + ni * 8 + fc * 2;
                __half2 h0 = __floats2half2_rn(d[mi][ni][0], d[mi][ni][1]);
                __half2 h1 = __floats2half2_rn(d[mi][ni][2], d[mi][ni][3]);
                *(__half2*)&C[(size_t)row * N + col] = h0;
                *(__half2*)&C[(size_t)(row + 8) * N + col] = h1;
            }
        }
    } else {
        float* C = (float*)Cv;
#pragma unroll
        for (int mi = 0; mi < 4; mi++) {
            const int row = bm + warp_m * 64 + mi * 16 + fr;
#pragma unroll
            for (int ni = 0; ni < 8; ni++) {
                const int col = bn + warp_n * 64 + ni * 8 + fc * 2;
                float2 v0 = make_float2(d[mi][ni][0], d[mi][ni][1]);
                float2 v1 = make_float2(d[mi][ni][2], d[mi][ni][3]);
                if (doRound) {
                    v0.x = round_tf32(v0.x); v0.y = round_tf32(v0.y);
                    v1.x = round_tf32(v1.x); v1.y = round_tf32(v1.y);
                }
                *(float2*)&C[(size_t)row * N + col] = v0;
                *(float2*)&C[(size_t)(row + 8) * N + col] = v1;
            }
        }
    }
}

// ---------------------------------------------------------------------------
// RoPE in-place on fp16 Q and K laid out [T, H*D]. Q also scaled by kScale.
// ---------------------------------------------------------------------------
__global__ void rope_kernel(__half* __restrict__ Q, __half* __restrict__ K) {
    const int t = blockIdx.x;
    const float ft = (float)t;
    for (int p = threadIdx.x; p < kH * 64; p += blockDim.x) {
        const int h = p >> 6;
        const int i = p & 63;
        const float inv = __expf(-(float)i * 0.14391157f);
        float s, c;
        sincosf(ft * inv, &s, &c);
        const size_t base = (size_t)t * kC + h * kD;
        {
            float x1 = __half2float(Q[base + i]);
            float x2 = __half2float(Q[base + 64 + i]);
            Q[base + i]      = __float2half_rn((x1 * c - x2 * s) * kScale);
            Q[base + 64 + i] = __float2half_rn((x2 * c + x1 * s) * kScale);
        }
        {
            float x1 = __half2float(K[base + i]);
            float x2 = __half2float(K[base + 64 + i]);
            K[base + i]      = __float2half_rn(x1 * c - x2 * s);
            K[base + 64 + i] = __float2half_rn(x2 * c + x1 * s);
        }
    }
}

// ---------------------------------------------------------------------------
// Tensor-core block-sparse flash attention, fp16 QK + tf32 PV.
// One CTA per (q-block, head): 64 q rows, 128 threads / 4 warps, 2 CTAs/SM.
// QK warp tile 32x32 (grid 2x2), m16n8k16 fp16 (half the HMMA count);
// PV warp tile 32x64 (2x2), tf32 with fp32 P and V (proven path).
// Separate K (fp16) and V (fp32) buffers -> R7-style cp.async pipelining:
// K(i+1) issued after QK(i), V(i+1) issued after PV(i).
// allowed(qb,kb) = kb <= qb && (qb-kb <= 16 || kb < 2 || (kb & 3) == 0).
// ---------------------------------------------------------------------------
constexpr int AQLDH = 136;   // Q/K rows in halfs (272B)
constexpr int AVLD = 136;    // V rows in floats
constexpr int APLD = 68;     // S/P rows in floats
constexpr int QS_OFF = 0;                          // 64*136*2 = 17408
constexpr int KS_OFF = QS_OFF + 64 * AQLDH * 2;    // 17408
constexpr int VS_OFF = KS_OFF + 64 * AQLDH * 2;    // 34816
constexpr int PS_OFF = VS_OFF + 64 * AVLD * 4;     // 69632
constexpr int CR_OFF = PS_OFF + 64 * APLD * 4;     // 87040
constexpr int ATTN_SMEM_BYTES = CR_OFF + 64 * 4;   // 87296

__global__ __launch_bounds__(128, 2) void attn_h(const __half* __restrict__ Q,
                                                 const __half* __restrict__ K,
                                                 const float* __restrict__ V,
                                                 __half* __restrict__ Ctx) {
    extern __shared__ char smc[];
    const uint32_t sb = smem_u32(smc);
    float* Ps = (float*)(smc + PS_OFF);
    float* Cr = (float*)(smc + CR_OFF);

    const int qb = (gridDim.x - 1) - blockIdx.x;   // heavy-first
    const int h = blockIdx.y;
    const int tid = threadIdx.x;
    const int lane = tid & 31;
    const int wid = tid >> 5;      // 0..3
    const int wm = wid & 1;        // rows wm*32
    const int wn = wid >> 1;       // QK cols wn*32 ; PV dims wn*64
    const int fr = lane >> 2;
    const int fc = lane & 3;
    const int srow = tid >> 1;     // softmax row 0..63
    const int shalf = tid & 1;     // softmax col half

    auto is_allowed = [&](int t) {
        return (t <= qb) && (((qb - t) <= 16) || (t < 2) || ((t & 3) == 0));
    };

    auto issueK = [&](int t) {
        // 64 rows x 256B = 1024 chunks; 8 per thread
#pragma unroll
        for (int j = 0; j < 8; j++) {
            const int idx = tid + j * 128;
            const int rr = idx >> 4;
            const int ch = idx & 15;
            cp_async16(sb + KS_OFF + (uint32_t)rr * (AQLDH * 2) + ch * 16,
                       &K[(size_t)(t * 64 + rr) * kC + h * kD + ch * 8]);
        }
        CP_COMMIT();
    };
    auto issueV = [&](int t) {
        // 64 rows x 512B = 2048 chunks; 16 per thread
#pragma unroll
        for (int j = 0; j < 16; j++) {
            const int idx = tid + j * 128;
            const int rr = idx >> 5;
            const int ch = idx & 31;
            cp_async16(sb + VS_OFF + (uint32_t)rr * (AVLD * 4) + ch * 16,
                       &V[(size_t)(t * 64 + rr) * kC + h * kD + ch * 4]);
        }
        CP_COMMIT();
    };

    // Prologue: Q (group), K0 (group), V0 (group)
#pragma unroll
    for (int j = 0; j < 8; j++) {
        const int idx = tid + j * 128;
        const int rr = idx >> 4;
        const int ch = idx & 15;
        cp_async16(sb + QS_OFF + (uint32_t)rr * (AQLDH * 2) + ch * 16,
                   &Q[(size_t)(qb * 64 + rr) * kC + h * kD + ch * 8]);
    }
    CP_COMMIT();
    int kb = 0;
    issueK(kb);
    issueV(kb);

    float m = -INFINITY, l = 0.0f;
    float o[2][8][4];
#pragma unroll
    for (int mi = 0; mi < 2; mi++)
#pragma unroll
        for (int ni = 0; ni < 8; ni++)
#pragma unroll
            for (int j = 0; j < 4; j++) o[mi][ni][j] = 0.0f;

    const uint32_t* Qw = (const uint32_t*)(smc + QS_OFF);   // LD 68 words
    const uint32_t* Kw = (const uint32_t*)(smc + KS_OFF);
    const uint32_t* Vw = (const uint32_t*)(smc + VS_OFF);   // fp32, LD 136
    const uint32_t* Pw = (const uint32_t*)(smc + PS_OFF);   // fp32, LD 68

    while (true) {
        int kbn = kb;
        for (int t = kb + 1; t <= qb; t++) {
            if (is_allowed(t)) { kbn = t; break; }
        }

        // wait for Q+K(kb); V(kb) may still be in flight
        asm volatile("cp.async.wait_group 1;" ::: "memory");
        __syncthreads();

        // ---- S = Q @ K^T (64x64), fp16 m16n8k16, 8 k-steps ----
        float s[2][4][4];
#pragma unroll
        for (int mi = 0; mi < 2; mi++)
#pragma unroll
            for (int ni = 0; ni < 4; ni++)
#pragma unroll
                for (int j = 0; j < 4; j++) s[mi][ni][j] = 0.0f;

#pragma unroll
        for (int kk = 0; kk < 8; kk++) {
            const int c0 = kk * 8 + fc;
            uint32_t a[2][4];
#pragma unroll
            for (int mi = 0; mi < 2; mi++) {
                const int r0 = wm * 32 + mi * 16 + fr;
                a[mi][0] = Qw[r0 * 68 + c0];
                a[mi][1] = Qw[(r0 + 8) * 68 + c0];
                a[mi][2] = Qw[r0 * 68 + c0 + 4];
                a[mi][3] = Qw[(r0 + 8) * 68 + c0 + 4];
            }
            uint32_t b[4][2];
#pragma unroll
            for (int ni = 0; ni < 4; ni++) {
                const int n0 = wn * 32 + ni * 8 + fr;
                b[ni][0] = Kw[n0 * 68 + c0];
                b[ni][1] = Kw[n0 * 68 + c0 + 4];
            }
#pragma unroll
            for (int mi = 0; mi < 2; mi++)
#pragma unroll
                for (int ni = 0; ni < 4; ni++)
                    mma_f16(s[mi][ni], a[mi], b[ni]);
        }

        // Store S fragments (fp32)
#pragma unroll
        for (int mi = 0; mi < 2; mi++) {
            const int r = wm * 32 + mi * 16 + fr;
#pragma unroll
            for (int ni = 0; ni < 4; ni++) {
                const int c = wn * 32 + ni * 8 + fc * 2;
                *(float2*)&Ps[r * APLD + c] = make_float2(s[mi][ni][0], s[mi][ni][1]);
                *(float2*)&Ps[(r + 8) * APLD + c] = make_float2(s[mi][ni][2], s[mi][ni][3]);
            }
        }
        __syncthreads();   // K reads + S writes done

        // prefetch next K (overlaps softmax + PV)
        issueK(kbn);

        // ---- scalar online softmax (row srow, cols shalf*32..+31) ----
        {
            float* prow = &Ps[srow * APLD + shalf * 32];
            float4 sv[8];
#pragma unroll
            for (int j = 0; j < 8; j++) sv[j] = *(const float4*)&prow[j * 4];
            float lm = -INFINITY;
#pragma unroll
            for (int j = 0; j < 8; j++)
                lm = fmaxf(lm, fmaxf(fmaxf(sv[j].x, sv[j].y), fmaxf(sv[j].z, sv[j].w)));
            lm = fmaxf(lm, __shfl_xor_sync(0xFFFFFFFFu, lm, 1));
            const float mnew = fmaxf(m, lm);
            const float corr = __expf(m - mnew);
            float rs = 0.0f;
#pragma unroll
            for (int j = 0; j < 8; j++) {
                sv[j].x = round_tf32(__expf(sv[j].x - mnew));
                sv[j].y = round_tf32(__expf(sv[j].y - mnew));
                sv[j].z = round_tf32(__expf(sv[j].z - mnew));
                sv[j].w = round_tf32(__expf(sv[j].w - mnew));
                rs += (sv[j].x + sv[j].y) + (sv[j].z + sv[j].w);
                *(float4*)&prow[j * 4] = sv[j];
            }
            rs += __shfl_xor_sync(0xFFFFFFFFu, rs, 1);
            l = l * corr + rs;
            m = mnew;
            if (shalf == 0) Cr[srow] = corr;
        }

        // wait for V(kb) (K(kbn) stays in flight), then publish P/Cr/V
        asm volatile("cp.async.wait_group 1;" ::: "memory");
        __syncthreads();

        // ---- O = O*corr + P @ V (64x128), tf32, 8 k-steps ----
#pragma unroll
        for (int mi = 0; mi < 2; mi++) {
            const float c0r = Cr[wm * 32 + mi * 16 + fr];
            const float c1r = Cr[wm * 32 + mi * 16 + 8 + fr];
#pragma unroll
            for (int ni = 0; ni < 8; ni++) {
                o[mi][ni][0] *= c0r; o[mi][ni][1] *= c0r;
                o[mi][ni][2] *= c1r; o[mi][ni][3] *= c1r;
            }
        }
#pragma unroll
        for (int kk = 0; kk < 8; kk++) {
            const int c0 = kk * 8 + fc;
            uint32_t a[2][4];
#pragma unroll
            for (int mi = 0; mi < 2; mi++) {
                const int r0 = wm * 32 + mi * 16 + fr;
                a[mi][0] = Pw[r0 * APLD + c0];
                a[mi][1] = Pw[(r0 + 8) * APLD + c0];
                a[mi][2] = Pw[r0 * APLD + c0 + 4];
                a[mi][3] = Pw[(r0 + 8) * APLD + c0 + 4];
            }
            uint32_t b[8][2];
#pragma unroll
            for (int ni = 0; ni < 8; ni++) {
                const int n0 = wn * 64 + ni * 8 + fr;
                b[ni][0] = Vw[c0 * AVLD + n0];
                b[ni][1] = Vw[(c0 + 4) * AVLD + n0];
            }
#pragma unroll
            for (int mi = 0; mi < 2; mi++)
#pragma unroll
                for (int ni = 0; ni < 8; ni++)
                    mma_tf32(o[mi][ni], a[mi], b[ni]);
        }
        __syncthreads();   // V/P reads done

        // prefetch next V (overlaps next tile's QK + softmax)
        issueV(kbn);

        if (kbn == kb) break;
        kb = kbn;
    }

    // Drain, publish 1/l, normalize + store fp16
    asm volatile("cp.async.wait_group 0;" ::: "memory");
    __syncthreads();
    if (shalf == 0) Cr[srow] = 1.0f / l;
    __syncthreads();
#pragma unroll
    for (int mi = 0; mi < 2; mi++) {
        const float inv0 = Cr[wm * 32 + mi * 16 + fr];
        const float inv1 = Cr[wm * 32 + mi * 16 + 8 + fr];
        const int row0 = qb * 64 + wm * 32 + mi * 16 + fr;
#pragma unroll
        for (int ni = 0; ni < 8; ni++) {
            const int col = h * kD + wn * 64 + ni * 8 + fc * 2;
            __half2 h0 = __floats2half2_rn(o[mi][ni][0] * inv0, o[mi][ni][1] * inv0);
            __half2 h1 = __floats2half2_rn(o[mi][ni][2] * inv1, o[mi][ni][3] * inv1);
            *(__half2*)&Ctx[(size_t)row0 * kC + col] = h0;
            *(__half2*)&Ctx[(size_t)(row0 + 8) * kC + col] = h1;
        }
    }
}

// ---------------------------------------------------------------------------
extern "C" void kernel_launch(void* const* d_in, const int* in_sizes, int n_in,
                              void* d_out, int out_size) {
    const float* x  = (const float*)d_in[0];
    const float* wq = (const float*)d_in[1];
    const float* wk = (const float*)d_in[2];
    const float* wv = (const float*)d_in[3];
    const float* wo = (const float*)d_in[4];
    float* out = (float*)d_out;

    __half *xh, *wh, *qh, *kh, *ch;
    float* vp;
    cudaGetSymbolAddress((void**)&xh, g_xh);
    cudaGetSymbolAddress((void**)&wh, g_wh);
    cudaGetSymbolAddress((void**)&qh, g_qh);
    cudaGetSymbolAddress((void**)&kh, g_kh);
    cudaGetSymbolAddress((void**)&vp, g_v);
    cudaGetSymbolAddress((void**)&ch, g_ch);

    cudaFuncSetAttribute(gemm_h3, cudaFuncAttributeMaxDynamicSharedMemorySize,
                         GEMM_SMEM_BYTES);
    cudaFuncSetAttribute(attn_h, cudaFuncAttributeMaxDynamicSharedMemorySize,
                         ATTN_SMEM_BYTES);

    const int CC = kC * kC;

    convert_all<<<dim3(kT * kC / 4 / 256, 5), 256>>>(x, wq, wk, wv, wo, xh, wh);

    // Fused QKV projection: q,k -> fp16 (halfMask bits 0,1); v -> fp32
    // tf32-rounded (roundMask bit 2).
    gemm_h3<<<dim3(kC / 128, kT / 128, 3), 128, GEMM_SMEM_BYTES>>>(
        xh, wh + 0 * CC, wh + 1 * CC, wh + 2 * CC,
        qh, kh, vp, kT, kC, kC, 3u, 4u);

    rope_kernel<<<kT, 256>>>(qh, kh);

    attn_h<<<dim3(kT / 64, kH), 128, ATTN_SMEM_BYTES>>>(qh, kh, vp, ch);

    // Output projection: fp16 in, fp32 raw out
    gemm_h3<<<dim3(kC / 128, kT / 128, 1), 128, GEMM_SMEM_BYTES>>>(
        ch, wh + 3 * CC, wh + 3 * CC, wh + 3 * CC,
        out, out, out, kT, kC, kC, 0u, 0u);
}

// round 13
// speedup vs baseline: 1.7123x; 1.0911x over previous
#include <cuda_runtime.h>
#include <cuda_fp16.h>
#include <math.h>
#include <stdint.h>

// Problem constants
constexpr int kT = 4096;
constexpr int kC = 2048;
constexpr int kH = 16;
constexpr int kD = 128;
constexpr float kScale = 0.08838834764831845f;

// Scratch (device globals — no cudaMalloc allowed)
__device__ __half g_xh[kT * kC];        // x in fp16
__device__ __half g_wh[4 * kC * kC];    // wq,wk,wv,wo in fp16
__device__ __half g_qh[kT * kC];        // q fp16 (rope'd, scaled)
__device__ __half g_kh[kT * kC];        // k fp16 (rope'd)
__device__ __half g_vh[kT * kC];        // v fp16 [T][C]
__device__ __half g_vt[kC * kT];        // v fp16 transposed [C][T]
__device__ __half g_ch[kT * kC];        // attention output fp16

// ---------------------------------------------------------------------------
__device__ __forceinline__ uint32_t smem_u32(const void* p) {
    uint32_t a;
    asm("{ .reg .u64 t; cvta.to.shared.u64 t, %1; cvt.u32.u64 %0, t; }"
        : "=r"(a) : "l"(p));
    return a;
}

__device__ __forceinline__ void cp_async16(uint32_t saddr, const void* gaddr) {
    asm volatile("cp.async.cg.shared.global [%0], [%1], 16;"
                 :: "r"(saddr), "l"(gaddr));
}
#define CP_COMMIT() asm volatile("cp.async.commit_group;" ::: "memory")

// mma.sync m16n8k16 fp16: D(16x8 f32) += A(16x16 f16) * B(16x8 f16)
__device__ __forceinline__ void mma_f16(float* d, const uint32_t* a,
                                        const uint32_t* b) {
    asm volatile(
        "mma.sync.aligned.m16n8k16.row.col.f32.f16.f16.f32 "
        "{%0,%1,%2,%3}, {%4,%5,%6,%7}, {%8,%9}, {%0,%1,%2,%3};"
        : "+f"(d[0]), "+f"(d[1]), "+f"(d[2]), "+f"(d[3])
        : "r"(a[0]), "r"(a[1]), "r"(a[2]), "r"(a[3]), "r"(b[0]), "r"(b[1]));
}

// ---------------------------------------------------------------------------
// Fused fp32 -> fp16 conversion: y=0 -> x, y in 1..4 -> weights.
// ---------------------------------------------------------------------------
__global__ void convert_all(const float* __restrict__ x,
                            const float* __restrict__ wq,
                            const float* __restrict__ wk,
                            const float* __restrict__ wv,
                            const float* __restrict__ wo,
                            __half* __restrict__ xh, __half* __restrict__ wh) {
    const int y = blockIdx.y;
    const float* src;
    __half* dst;
    int n4;
    const int CC = kC * kC;
    if (y == 0) { src = x;  dst = xh;           n4 = kT * kC / 4; }
    else if (y == 1) { src = wq; dst = wh;          n4 = CC / 4; }
    else if (y == 2) { src = wk; dst = wh + CC;     n4 = CC / 4; }
    else if (y == 3) { src = wv; dst = wh + 2 * CC; n4 = CC / 4; }
    else             { src = wo; dst = wh + 3 * CC; n4 = CC / 4; }
    int i = blockIdx.x * blockDim.x + threadIdx.x;
    if (i < n4) {
        float4 v = ((const float4*)src)[i];
        __half2 h0 = __floats2half2_rn(v.x, v.y);
        __half2 h1 = __floats2half2_rn(v.z, v.w);
        uint2 u;
        u.x = *(uint32_t*)&h0;
        u.y = *(uint32_t*)&h1;
        *(uint2*)(dst + i * 4) = u;
    }
}

// ---------------------------------------------------------------------------
// FP16 tensor-core GEMM: C[m,n] = sum_k A[m,k] * B[n,k], fp32 accumulate.
// CTA tile 128x128x32, 4 warps, warp tile 64x64, m16n8k16.
// 3-stage cp.async; smem rows 32 halfs padded to 40 (conflict-free).
// blockIdx.z selects (B, C). halfMask bit z: output fp16 (else fp32).
// ---------------------------------------------------------------------------
constexpr int GLDH = 40;                                 // halfs per row
constexpr int GSTAGE_HALFS = 2 * 128 * GLDH;             // 10240 halfs = 20KB
constexpr int GEMM_SMEM_BYTES = 3 * GSTAGE_HALFS * 2;    // 61440

__global__ __launch_bounds__(128, 2) void gemm_h3(
    const __half* __restrict__ A,
    const __half* __restrict__ B0, const __half* __restrict__ B1,
    const __half* __restrict__ B2,
    void* __restrict__ C0, void* __restrict__ C1, void* __restrict__ C2,
    int M, int N, int K, unsigned halfMask) {
    const __half* B = (blockIdx.z == 0) ? B0 : (blockIdx.z == 1) ? B1 : B2;
    void* Cv = (blockIdx.z == 0) ? C0 : (blockIdx.z == 1) ? C1 : C2;
    const bool halfOut = (halfMask >> blockIdx.z) & 1u;

    extern __shared__ __half smh[];
    const uint32_t sb = smem_u32(smh);
    const int tid = threadIdx.x;
    const int lane = tid & 31;
    const int wid = tid >> 5;      // 0..3
    const int warp_m = wid & 1;    // rows warp_m*64
    const int warp_n = wid >> 1;   // cols warp_n*64
    const int bm = blockIdx.y * 128;
    const int bn = blockIdx.x * 128;

    float d[4][8][4];
#pragma unroll
    for (int mi = 0; mi < 4; mi++)
#pragma unroll
        for (int ni = 0; ni < 8; ni++)
#pragma unroll
            for (int j = 0; j < 4; j++) d[mi][ni][j] = 0.0f;

    const int nStages = K / 32;

    auto prefetch = [&](int s) {
        const int buf = s % 3;
        const uint32_t ab = sb + buf * GSTAGE_HALFS * 2;
        const uint32_t bb = ab + 128 * GLDH * 2;
        const int k0 = s * 32;
#pragma unroll
        for (int j = 0; j < 4; j++) {
            const int idx = tid + j * 128;
            const int row = idx >> 2;
            const int ch = idx & 3;
            const uint32_t soff = (uint32_t)row * 80 + ch * 16;
            cp_async16(ab + soff, &A[(size_t)(bm + row) * K + k0 + ch * 8]);
            cp_async16(bb + soff, &B[(size_t)(bn + row) * K + k0 + ch * 8]);
        }
        CP_COMMIT();
    };

    prefetch(0);
    prefetch(1);

    const int fr = lane >> 2;
    const int fc = lane & 3;

    for (int s = 0; s < nStages; s++) {
        if (s < nStages - 1) {
            asm volatile("cp.async.wait_group 1;" ::: "memory");
        } else {
            asm volatile("cp.async.wait_group 0;" ::: "memory");
        }
        __syncthreads();
        if (s + 2 < nStages) prefetch(s + 2);

        const int buf = s % 3;
        const uint32_t* As = (const uint32_t*)(smh + buf * GSTAGE_HALFS);
        const uint32_t* Bs = As + 128 * (GLDH / 2);

#pragma unroll
        for (int kk = 0; kk < 2; kk++) {
            const int c0 = kk * 8 + fc;
            uint32_t a[4][4];
#pragma unroll
            for (int mi = 0; mi < 4; mi++) {
                const int r0 = warp_m * 64 + mi * 16 + fr;
                a[mi][0] = As[r0 * 20 + c0];
                a[mi][1] = As[(r0 + 8) * 20 + c0];
                a[mi][2] = As[r0 * 20 + c0 + 4];
                a[mi][3] = As[(r0 + 8) * 20 + c0 + 4];
            }
            uint32_t b[8][2];
#pragma unroll
            for (int ni = 0; ni < 8; ni++) {
                const int n0 = warp_n * 64 + ni * 8 + fr;
                b[ni][0] = Bs[n0 * 20 + c0];
                b[ni][1] = Bs[n0 * 20 + c0 + 4];
            }
#pragma unroll
            for (int mi = 0; mi < 4; mi++)
#pragma unroll
                for (int ni = 0; ni < 8; ni++)
                    mma_f16(d[mi][ni], a[mi], b[ni]);
        }
    }

    if (halfOut) {
        __half* C = (__half*)Cv;
#pragma unroll
        for (int mi = 0; mi < 4; mi++) {
            const int row = bm + warp_m * 64 + mi * 16 + fr;
#pragma unroll
            for (int ni = 0; ni < 8; ni++) {
                const int col = bn + warp_n * 64 + ni * 8 + fc * 2;
                __half2 h0 = __floats2half2_rn(d[mi][ni][0], d[mi][ni][1]);
                __half2 h1 = __floats2half2_rn(d[mi][ni][2], d[mi][ni][3]);
                *(__half2*)&C[(size_t)row * N + col] = h0;
                *(__half2*)&C[(size_t)(row + 8) * N + col] = h1;
            }
        }
    } else {
        float* C = (float*)Cv;
#pragma unroll
        for (int mi = 0; mi < 4; mi++) {
            const int row = bm + warp_m * 64 + mi * 16 + fr;
#pragma unroll
            for (int ni = 0; ni < 8; ni++) {
                const int col = bn + warp_n * 64 + ni * 8 + fc * 2;
                *(float2*)&C[(size_t)row * N + col] =
                    make_float2(d[mi][ni][0], d[mi][ni][1]);
                *(float2*)&C[(size_t)(row + 8) * N + col] =
                    make_float2(d[mi][ni][2], d[mi][ni][3]);
            }
        }
    }
}

// ---------------------------------------------------------------------------
// V transpose: Vt[c][t] = V[t][c], fp16, 64x64 smem tiles.
// ---------------------------------------------------------------------------
__global__ void transpose_v(const __half* __restrict__ V,
                            __half* __restrict__ Vt) {
    __shared__ __half tile[64 * 72];
    const int c0 = blockIdx.x * 64;
    const int t0 = blockIdx.y * 64;
    const int tid = threadIdx.x;
#pragma unroll
    for (int j = 0; j < 2; j++) {
        const int idx = (tid + j * 256) * 8;   // 0..4088
        const int r = idx >> 6;                // token row 0..63
        const int c = idx & 63;                // channel col (multiple of 8)
        uint4 v = *(const uint4*)&V[(size_t)(t0 + r) * kC + c0 + c];
        const __half* hp = (const __half*)&v;
#pragma unroll
        for (int e = 0; e < 8; e++) tile[(c + e) * 72 + r] = hp[e];
    }
    __syncthreads();
#pragma unroll
    for (int j = 0; j < 2; j++) {
        const int idx = (tid + j * 256) * 8;
        const int r = idx >> 6;                // channel row 0..63
        const int cc = idx & 63;               // token col (multiple of 8)
        uint4 v;
        __half* hp = (__half*)&v;
#pragma unroll
        for (int e = 0; e < 8; e++) hp[e] = tile[r * 72 + cc + e];
        *(uint4*)&Vt[(size_t)(c0 + r) * kT + t0 + cc] = v;
    }
}

// ---------------------------------------------------------------------------
// RoPE in-place on fp16 Q and K laid out [T, H*D]. Q also scaled by kScale.
// ---------------------------------------------------------------------------
__global__ void rope_kernel(__half* __restrict__ Q, __half* __restrict__ K) {
    const int t = blockIdx.x;
    const float ft = (float)t;
    for (int p = threadIdx.x; p < kH * 64; p += blockDim.x) {
        const int h = p >> 6;
        const int i = p & 63;
        const float inv = __expf(-(float)i * 0.14391157f);
        float s, c;
        sincosf(ft * inv, &s, &c);
        const size_t base = (size_t)t * kC + h * kD;
        {
            float x1 = __half2float(Q[base + i]);
            float x2 = __half2float(Q[base + 64 + i]);
            Q[base + i]      = __float2half_rn((x1 * c - x2 * s) * kScale);
            Q[base + 64 + i] = __float2half_rn((x2 * c + x1 * s) * kScale);
        }
        {
            float x1 = __half2float(K[base + i]);
            float x2 = __half2float(K[base + 64 + i]);
            K[base + i]      = __float2half_rn(x1 * c - x2 * s);
            K[base + 64 + i] = __float2half_rn(x2 * c + x1 * s);
        }
    }
}

// ---------------------------------------------------------------------------
// Tensor-core block-sparse flash attention, FULL fp16 (QK and PV m16n8k16).
// One CTA per (q-block, head): 64 q rows, 128 threads / 4 warps, 2 CTAs/SM.
// QK warp tile 32x32 (grid 2x2), PV warp tile 32x64 (2x2).
// V comes pre-transposed (Vt[c][t]) so the PV B-fragment gather has k
// contiguous — same index pattern as the K fragments, conflict-free.
// S kept fp32; P stored fp16. cp.async pipeline: K(i+1) after QK(i),
// V(i+1) after PV(i).
// ---------------------------------------------------------------------------
constexpr int AQLDH = 136;   // Q/K rows in halfs
constexpr int AVLDH = 72;    // Vt rows in halfs (64 + pad 8)
constexpr int APLDH = 72;    // P rows in halfs
constexpr int ASLD = 68;     // S rows in floats
constexpr int QS_OFF = 0;                          // 17408
constexpr int KS_OFF = QS_OFF + 64 * AQLDH * 2;    // 17408
constexpr int VT_OFF = KS_OFF + 64 * AQLDH * 2;    // 34816
constexpr int SS_OFF = VT_OFF + 128 * AVLDH * 2;   // 53248
constexpr int PH_OFF = SS_OFF + 64 * ASLD * 4;     // 70656
constexpr int CR_OFF = PH_OFF + 64 * APLDH * 2;    // 79872
constexpr int ATTN_SMEM_BYTES = CR_OFF + 64 * 4;   // 80128

__global__ __launch_bounds__(128, 2) void attn_h(const __half* __restrict__ Q,
                                                 const __half* __restrict__ K,
                                                 const __half* __restrict__ Vt,
                                                 __half* __restrict__ Ctx) {
    extern __shared__ char smc[];
    const uint32_t sb = smem_u32(smc);
    float* Ss = (float*)(smc + SS_OFF);
    __half* Ph = (__half*)(smc + PH_OFF);
    float* Cr = (float*)(smc + CR_OFF);

    const int qb = (gridDim.x - 1) - blockIdx.x;   // heavy-first
    const int h = blockIdx.y;
    const int tid = threadIdx.x;
    const int lane = tid & 31;
    const int wid = tid >> 5;      // 0..3
    const int wm = wid & 1;        // rows wm*32
    const int wn = wid >> 1;       // QK cols wn*32 ; PV dims wn*64
    const int fr = lane >> 2;
    const int fc = lane & 3;
    const int srow = tid >> 1;     // softmax row 0..63
    const int shalf = tid & 1;     // softmax col half

    auto is_allowed = [&](int t) {
        return (t <= qb) && (((qb - t) <= 16) || (t < 2) || ((t & 3) == 0));
    };

    auto issueK = [&](int t) {
        // 64 rows x 256B = 1024 chunks; 8 per thread
#pragma unroll
        for (int j = 0; j < 8; j++) {
            const int idx = tid + j * 128;
            const int rr = idx >> 4;
            const int ch = idx & 15;
            cp_async16(sb + KS_OFF + (uint32_t)rr * (AQLDH * 2) + ch * 16,
                       &K[(size_t)(t * 64 + rr) * kC + h * kD + ch * 8]);
        }
        CP_COMMIT();
    };
    auto issueV = [&](int t) {
        // Vt tile: 128 dim-rows x 128B = 1024 chunks; 8 per thread
#pragma unroll
        for (int j = 0; j < 8; j++) {
            const int idx = tid + j * 128;
            const int rr = idx >> 3;     // dim 0..127
            const int ch = idx & 7;
            cp_async16(sb + VT_OFF + (uint32_t)rr * (AVLDH * 2) + ch * 16,
                       &Vt[(size_t)(h * kD + rr) * kT + t * 64 + ch * 8]);
        }
        CP_COMMIT();
    };

    // Prologue: Q (group), K0 (group), V0 (group)
#pragma unroll
    for (int j = 0; j < 8; j++) {
        const int idx = tid + j * 128;
        const int rr = idx >> 4;
        const int ch = idx & 15;
        cp_async16(sb + QS_OFF + (uint32_t)rr * (AQLDH * 2) + ch * 16,
                   &Q[(size_t)(qb * 64 + rr) * kC + h * kD + ch * 8]);
    }
    CP_COMMIT();
    int kb = 0;
    issueK(kb);
    issueV(kb);

    float m = -INFINITY, l = 0.0f;
    float o[2][8][4];
#pragma unroll
    for (int mi = 0; mi < 2; mi++)
#pragma unroll
        for (int ni = 0; ni < 8; ni++)
#pragma unroll
            for (int j = 0; j < 4; j++) o[mi][ni][j] = 0.0f;

    const uint32_t* Qw = (const uint32_t*)(smc + QS_OFF);   // LD 68 words
    const uint32_t* Kw = (const uint32_t*)(smc + KS_OFF);   // LD 68 words
    const uint32_t* Vw = (const uint32_t*)(smc + VT_OFF);   // LD 36 words
    const uint32_t* Pw = (const uint32_t*)(smc + PH_OFF);   // LD 36 words

    while (true) {
        int kbn = kb;
        for (int t = kb + 1; t <= qb; t++) {
            if (is_allowed(t)) { kbn = t; break; }
        }

        // wait for Q+K(kb); V(kb) may still be in flight
        asm volatile("cp.async.wait_group 1;" ::: "memory");
        __syncthreads();

        // ---- S = Q @ K^T (64x64), fp16, 8 k-steps ----
        float s[2][4][4];
#pragma unroll
        for (int mi = 0; mi < 2; mi++)
#pragma unroll
            for (int ni = 0; ni < 4; ni++)
#pragma unroll
                for (int j = 0; j < 4; j++) s[mi][ni][j] = 0.0f;

#pragma unroll
        for (int kk = 0; kk < 8; kk++) {
            const int c0 = kk * 8 + fc;
            uint32_t a[2][4];
#pragma unroll
            for (int mi = 0; mi < 2; mi++) {
                const int r0 = wm * 32 + mi * 16 + fr;
                a[mi][0] = Qw[r0 * 68 + c0];
                a[mi][1] = Qw[(r0 + 8) * 68 + c0];
                a[mi][2] = Qw[r0 * 68 + c0 + 4];
                a[mi][3] = Qw[(r0 + 8) * 68 + c0 + 4];
            }
            uint32_t b[4][2];
#pragma unroll
            for (int ni = 0; ni < 4; ni++) {
                const int n0 = wn * 32 + ni * 8 + fr;
                b[ni][0] = Kw[n0 * 68 + c0];
                b[ni][1] = Kw[n0 * 68 + c0 + 4];
            }
#pragma unroll
            for (int mi = 0; mi < 2; mi++)
#pragma unroll
                for (int ni = 0; ni < 4; ni++)
                    mma_f16(s[mi][ni], a[mi], b[ni]);
        }

        // Store S fragments (fp32)
#pragma unroll
        for (int mi = 0; mi < 2; mi++) {
            const int r = wm * 32 + mi * 16 + fr;
#pragma unroll
            for (int ni = 0; ni < 4; ni++) {
                const int c = wn * 32 + ni * 8 + fc * 2;
                *(float2*)&Ss[r * ASLD + c] = make_float2(s[mi][ni][0], s[mi][ni][1]);
                *(float2*)&Ss[(r + 8) * ASLD + c] = make_float2(s[mi][ni][2], s[mi][ni][3]);
            }
        }
        __syncthreads();   // K reads + S writes done

        // prefetch next K (overlaps softmax + PV)
        issueK(kbn);

        // ---- scalar online softmax (row srow, cols shalf*32..+31) ----
        {
            const float* srcrow = &Ss[srow * ASLD + shalf * 32];
            float4 sv[8];
#pragma unroll
            for (int j = 0; j < 8; j++) sv[j] = *(const float4*)&srcrow[j * 4];
            float lm = -INFINITY;
#pragma unroll
            for (int j = 0; j < 8; j++)
                lm = fmaxf(lm, fmaxf(fmaxf(sv[j].x, sv[j].y), fmaxf(sv[j].z, sv[j].w)));
            lm = fmaxf(lm, __shfl_xor_sync(0xFFFFFFFFu, lm, 1));
            const float mnew = fmaxf(m, lm);
            const float corr = __expf(m - mnew);
            float rs = 0.0f;
            __half* dstrow = &Ph[srow * APLDH + shalf * 32];
#pragma unroll
            for (int j = 0; j < 8; j++) {
                const float e0 = __expf(sv[j].x - mnew);
                const float e1 = __expf(sv[j].y - mnew);
                const float e2 = __expf(sv[j].z - mnew);
                const float e3 = __expf(sv[j].w - mnew);
                rs += (e0 + e1) + (e2 + e3);
                __half2 h0 = __floats2half2_rn(e0, e1);
                __half2 h1 = __floats2half2_rn(e2, e3);
                uint2 u;
                u.x = *(uint32_t*)&h0;
                u.y = *(uint32_t*)&h1;
                *(uint2*)&dstrow[j * 4] = u;
            }
            rs += __shfl_xor_sync(0xFFFFFFFFu, rs, 1);
            l = l * corr + rs;
            m = mnew;
            if (shalf == 0) Cr[srow] = corr;
        }

        // wait for V(kb) (K(kbn) stays in flight), then publish P/Cr/V
        asm volatile("cp.async.wait_group 1;" ::: "memory");
        __syncthreads();

        // ---- O = O*corr + P @ V (64x128), fp16, 4 k-steps ----
#pragma unroll
        for (int mi = 0; mi < 2; mi++) {
            const float c0r = Cr[wm * 32 + mi * 16 + fr];
            const float c1r = Cr[wm * 32 + mi * 16 + 8 + fr];
#pragma unroll
            for (int ni = 0; ni < 8; ni++) {
                o[mi][ni][0] *= c0r; o[mi][ni][1] *= c0r;
                o[mi][ni][2] *= c1r; o[mi][ni][3] *= c1r;
            }
        }
#pragma unroll
        for (int kk = 0; kk < 4; kk++) {
            const int c0 = kk * 8 + fc;
            uint32_t a[2][4];
#pragma unroll
            for (int mi = 0; mi < 2; mi++) {
                const int r0 = wm * 32 + mi * 16 + fr;
                a[mi][0] = Pw[r0 * 36 + c0];
                a[mi][1] = Pw[(r0 + 8) * 36 + c0];
                a[mi][2] = Pw[r0 * 36 + c0 + 4];
                a[mi][3] = Pw[(r0 + 8) * 36 + c0 + 4];
            }
            uint32_t b[8][2];
#pragma unroll
            for (int ni = 0; ni < 8; ni++) {
                const int n0 = wn * 64 + ni * 8 + fr;
                b[ni][0] = Vw[n0 * 36 + c0];
                b[ni][1] = Vw[n0 * 36 + c0 + 4];
            }
#pragma unroll
            for (int mi = 0; mi < 2; mi++)
#pragma unroll
                for (int ni = 0; ni < 8; ni++)
                    mma_f16(o[mi][ni], a[mi], b[ni]);
        }
        __syncthreads();   // V/P reads done

        // prefetch next V (overlaps next tile's QK + softmax)
        issueV(kbn);

        if (kbn == kb) break;
        kb = kbn;
    }

    // Drain, publish 1/l, normalize + store fp16
    asm volatile("cp.async.wait_group 0;" ::: "memory");
    __syncthreads();
    if (shalf == 0) Cr[srow] = 1.0f / l;
    __syncthreads();
#pragma unroll
    for (int mi = 0; mi < 2; mi++) {
        const float inv0 = Cr[wm * 32 + mi * 16 + fr];
        const float inv1 = Cr[wm * 32 + mi * 16 + 8 + fr];
        const int row0 = qb * 64 + wm * 32 + mi * 16 + fr;
#pragma unroll
        for (int ni = 0; ni < 8; ni++) {
            const int col = h * kD + wn * 64 + ni * 8 + fc * 2;
            __half2 h0 = __floats2half2_rn(o[mi][ni][0] * inv0, o[mi][ni][1] * inv0);
            __half2 h1 = __floats2half2_rn(o[mi][ni][2] * inv1, o[mi][ni][3] * inv1);
            *(__half2*)&Ctx[(size_t)row0 * kC + col] = h0;
            *(__half2*)&Ctx[(size_t)(row0 + 8) * kC + col] = h1;
        }
    }
}

// ---------------------------------------------------------------------------
extern "C" void kernel_launch(void* const* d_in, const int* in_sizes, int n_in,
                              void* d_out, int out_size) {
    const float* x  = (const float*)d_in[0];
    const float* wq = (const float*)d_in[1];
    const float* wk = (const float*)d_in[2];
    const float* wv = (const float*)d_in[3];
    const float* wo = (const float*)d_in[4];
    float* out = (float*)d_out;

    __half *xh, *wh, *qh, *kh, *vh, *vt, *ch;
    cudaGetSymbolAddress((void**)&xh, g_xh);
    cudaGetSymbolAddress((void**)&wh, g_wh);
    cudaGetSymbolAddress((void**)&qh, g_qh);
    cudaGetSymbolAddress((void**)&kh, g_kh);
    cudaGetSymbolAddress((void**)&vh, g_vh);
    cudaGetSymbolAddress((void**)&vt, g_vt);
    cudaGetSymbolAddress((void**)&ch, g_ch);

    cudaFuncSetAttribute(gemm_h3, cudaFuncAttributeMaxDynamicSharedMemorySize,
                         GEMM_SMEM_BYTES);
    cudaFuncSetAttribute(attn_h, cudaFuncAttributeMaxDynamicSharedMemorySize,
                         ATTN_SMEM_BYTES);

    const int CC = kC * kC;

    convert_all<<<dim3(kT * kC / 4 / 256, 5), 256>>>(x, wq, wk, wv, wo, xh, wh);

    // Fused QKV projection: q,k,v all fp16 outputs
    gemm_h3<<<dim3(kC / 128, kT / 128, 3), 128, GEMM_SMEM_BYTES>>>(
        xh, wh + 0 * CC, wh + 1 * CC, wh + 2 * CC,
        qh, kh, vh, kT, kC, kC, 7u);

    rope_kernel<<<kT, 256>>>(qh, kh);
    transpose_v<<<dim3(kC / 64, kT / 64), 256>>>(vh, vt);

    attn_h<<<dim3(kT / 64, kH), 128, ATTN_SMEM_BYTES>>>(qh, kh, vt, ch);

    // Output projection: fp16 in, fp32 out
    gemm_h3<<<dim3(kC / 128, kT / 128, 1), 128, GEMM_SMEM_BYTES>>>(
        ch, wh + 3 * CC, wh + 3 * CC, wh + 3 * CC,
        out, out, out, kT, kC, kC, 0u);
}

// round 14
// speedup vs baseline: 1.8063x; 1.0549x over previous
#include <cuda_runtime.h>
#include <cuda_fp16.h>
#include <math.h>
#include <stdint.h>

// Problem constants
constexpr int kT = 4096;
constexpr int kC = 2048;
constexpr int kH = 16;
constexpr int kD = 128;
constexpr float kScale = 0.08838834764831845f;

// Scratch (device globals — no cudaMalloc allowed)
__device__ __half g_xh[kT * kC];        // x in fp16
__device__ __half g_wh[4 * kC * kC];    // wq,wk,wv,wo in fp16
__device__ __half g_qh[kT * kC];        // q fp16 (rope'd, scaled)
__device__ __half g_kh[kT * kC];        // k fp16 (rope'd)
__device__ __half g_vh[kT * kC];        // v fp16 [T][C]
__device__ __half g_vt[kC * kT];        // v fp16 transposed [C][T]
__device__ __half g_ch[kT * kC];        // attention output fp16

// ---------------------------------------------------------------------------
__device__ __forceinline__ uint32_t smem_u32(const void* p) {
    uint32_t a;
    asm("{ .reg .u64 t; cvta.to.shared.u64 t, %1; cvt.u32.u64 %0, t; }"
        : "=r"(a) : "l"(p));
    return a;
}

__device__ __forceinline__ void cp_async16(uint32_t saddr, const void* gaddr) {
    asm volatile("cp.async.cg.shared.global [%0], [%1], 16;"
                 :: "r"(saddr), "l"(gaddr));
}
#define CP_COMMIT() asm volatile("cp.async.commit_group;" ::: "memory")

// mma.sync m16n8k16 fp16: D(16x8 f32) += A(16x16 f16) * B(16x8 f16)
__device__ __forceinline__ void mma_f16(float* d, const uint32_t* a,
                                        const uint32_t* b) {
    asm volatile(
        "mma.sync.aligned.m16n8k16.row.col.f32.f16.f16.f32 "
        "{%0,%1,%2,%3}, {%4,%5,%6,%7}, {%8,%9}, {%0,%1,%2,%3};"
        : "+f"(d[0]), "+f"(d[1]), "+f"(d[2]), "+f"(d[3])
        : "r"(a[0]), "r"(a[1]), "r"(a[2]), "r"(a[3]), "r"(b[0]), "r"(b[1]));
}

// ---------------------------------------------------------------------------
// Fused fp32 -> fp16 conversion: y=0 -> x, y in 1..4 -> weights.
// ---------------------------------------------------------------------------
__global__ void convert_all(const float* __restrict__ x,
                            const float* __restrict__ wq,
                            const float* __restrict__ wk,
                            const float* __restrict__ wv,
                            const float* __restrict__ wo,
                            __half* __restrict__ xh, __half* __restrict__ wh) {
    const int y = blockIdx.y;
    const float* src;
    __half* dst;
    int n4;
    const int CC = kC * kC;
    if (y == 0) { src = x;  dst = xh;           n4 = kT * kC / 4; }
    else if (y == 1) { src = wq; dst = wh;          n4 = CC / 4; }
    else if (y == 2) { src = wk; dst = wh + CC;     n4 = CC / 4; }
    else if (y == 3) { src = wv; dst = wh + 2 * CC; n4 = CC / 4; }
    else             { src = wo; dst = wh + 3 * CC; n4 = CC / 4; }
    int i = blockIdx.x * blockDim.x + threadIdx.x;
    if (i < n4) {
        float4 v = ((const float4*)src)[i];
        __half2 h0 = __floats2half2_rn(v.x, v.y);
        __half2 h1 = __floats2half2_rn(v.z, v.w);
        uint2 u;
        u.x = *(uint32_t*)&h0;
        u.y = *(uint32_t*)&h1;
        *(uint2*)(dst + i * 4) = u;
    }
}

// ---------------------------------------------------------------------------
// FP16 tensor-core GEMM (unchanged R13 config): C[m,n] = sum_k A[m,k]*B[n,k].
// CTA tile 128x128x32, 4 warps, warp tile 64x64, m16n8k16, 3-stage cp.async.
// ---------------------------------------------------------------------------
constexpr int GLDH = 40;
constexpr int GSTAGE_HALFS = 2 * 128 * GLDH;
constexpr int GEMM_SMEM_BYTES = 3 * GSTAGE_HALFS * 2;    // 61440

__global__ __launch_bounds__(128, 2) void gemm_h3(
    const __half* __restrict__ A,
    const __half* __restrict__ B0, const __half* __restrict__ B1,
    const __half* __restrict__ B2,
    void* __restrict__ C0, void* __restrict__ C1, void* __restrict__ C2,
    int M, int N, int K, unsigned halfMask) {
    const __half* B = (blockIdx.z == 0) ? B0 : (blockIdx.z == 1) ? B1 : B2;
    void* Cv = (blockIdx.z == 0) ? C0 : (blockIdx.z == 1) ? C1 : C2;
    const bool halfOut = (halfMask >> blockIdx.z) & 1u;

    extern __shared__ __half smh[];
    const uint32_t sb = smem_u32(smh);
    const int tid = threadIdx.x;
    const int lane = tid & 31;
    const int wid = tid >> 5;
    const int warp_m = wid & 1;
    const int warp_n = wid >> 1;
    const int bm = blockIdx.y * 128;
    const int bn = blockIdx.x * 128;

    float d[4][8][4];
#pragma unroll
    for (int mi = 0; mi < 4; mi++)
#pragma unroll
        for (int ni = 0; ni < 8; ni++)
#pragma unroll
            for (int j = 0; j < 4; j++) d[mi][ni][j] = 0.0f;

    const int nStages = K / 32;

    auto prefetch = [&](int s) {
        const int buf = s % 3;
        const uint32_t ab = sb + buf * GSTAGE_HALFS * 2;
        const uint32_t bb = ab + 128 * GLDH * 2;
        const int k0 = s * 32;
#pragma unroll
        for (int j = 0; j < 4; j++) {
            const int idx = tid + j * 128;
            const int row = idx >> 2;
            const int ch = idx & 3;
            const uint32_t soff = (uint32_t)row * 80 + ch * 16;
            cp_async16(ab + soff, &A[(size_t)(bm + row) * K + k0 + ch * 8]);
            cp_async16(bb + soff, &B[(size_t)(bn + row) * K + k0 + ch * 8]);
        }
        CP_COMMIT();
    };

    prefetch(0);
    prefetch(1);

    const int fr = lane >> 2;
    const int fc = lane & 3;

    for (int s = 0; s < nStages; s++) {
        if (s < nStages - 1) {
            asm volatile("cp.async.wait_group 1;" ::: "memory");
        } else {
            asm volatile("cp.async.wait_group 0;" ::: "memory");
        }
        __syncthreads();
        if (s + 2 < nStages) prefetch(s + 2);

        const int buf = s % 3;
        const uint32_t* As = (const uint32_t*)(smh + buf * GSTAGE_HALFS);
        const uint32_t* Bs = As + 128 * (GLDH / 2);

#pragma unroll
        for (int kk = 0; kk < 2; kk++) {
            const int c0 = kk * 8 + fc;
            uint32_t a[4][4];
#pragma unroll
            for (int mi = 0; mi < 4; mi++) {
                const int r0 = warp_m * 64 + mi * 16 + fr;
                a[mi][0] = As[r0 * 20 + c0];
                a[mi][1] = As[(r0 + 8) * 20 + c0];
                a[mi][2] = As[r0 * 20 + c0 + 4];
                a[mi][3] = As[(r0 + 8) * 20 + c0 + 4];
            }
            uint32_t b[8][2];
#pragma unroll
            for (int ni = 0; ni < 8; ni++) {
                const int n0 = warp_n * 64 + ni * 8 + fr;
                b[ni][0] = Bs[n0 * 20 + c0];
                b[ni][1] = Bs[n0 * 20 + c0 + 4];
            }
#pragma unroll
            for (int mi = 0; mi < 4; mi++)
#pragma unroll
                for (int ni = 0; ni < 8; ni++)
                    mma_f16(d[mi][ni], a[mi], b[ni]);
        }
    }

    if (halfOut) {
        __half* C = (__half*)Cv;
#pragma unroll
        for (int mi = 0; mi < 4; mi++) {
            const int row = bm + warp_m * 64 + mi * 16 + fr;
#pragma unroll
            for (int ni = 0; ni < 8; ni++) {
                const int col = bn + warp_n * 64 + ni * 8 + fc * 2;
                __half2 h0 = __floats2half2_rn(d[mi][ni][0], d[mi][ni][1]);
                __half2 h1 = __floats2half2_rn(d[mi][ni][2], d[mi][ni][3]);
                *(__half2*)&C[(size_t)row * N + col] = h0;
                *(__half2*)&C[(size_t)(row + 8) * N + col] = h1;
            }
        }
    } else {
        float* C = (float*)Cv;
#pragma unroll
        for (int mi = 0; mi < 4; mi++) {
            const int row = bm + warp_m * 64 + mi * 16 + fr;
#pragma unroll
            for (int ni = 0; ni < 8; ni++) {
                const int col = bn + warp_n * 64 + ni * 8 + fc * 2;
                *(float2*)&C[(size_t)row * N + col] =
                    make_float2(d[mi][ni][0], d[mi][ni][1]);
                *(float2*)&C[(size_t)(row + 8) * N + col] =
                    make_float2(d[mi][ni][2], d[mi][ni][3]);
            }
        }
    }
}

// ---------------------------------------------------------------------------
// V transpose: Vt[c][t] = V[t][c], fp16, 64x64 smem tiles.
// ---------------------------------------------------------------------------
__global__ void transpose_v(const __half* __restrict__ V,
                            __half* __restrict__ Vt) {
    __shared__ __half tile[64 * 72];
    const int c0 = blockIdx.x * 64;
    const int t0 = blockIdx.y * 64;
    const int tid = threadIdx.x;
#pragma unroll
    for (int j = 0; j < 2; j++) {
        const int idx = (tid + j * 256) * 8;
        const int r = idx >> 6;
        const int c = idx & 63;
        uint4 v = *(const uint4*)&V[(size_t)(t0 + r) * kC + c0 + c];
        const __half* hp = (const __half*)&v;
#pragma unroll
        for (int e = 0; e < 8; e++) tile[(c + e) * 72 + r] = hp[e];
    }
    __syncthreads();
#pragma unroll
    for (int j = 0; j < 2; j++) {
        const int idx = (tid + j * 256) * 8;
        const int r = idx >> 6;
        const int cc = idx & 63;
        uint4 v;
        __half* hp = (__half*)&v;
#pragma unroll
        for (int e = 0; e < 8; e++) hp[e] = tile[r * 72 + cc + e];
        *(uint4*)&Vt[(size_t)(c0 + r) * kT + t0 + cc] = v;
    }
}

// ---------------------------------------------------------------------------
// RoPE in-place on fp16 Q and K laid out [T, H*D]. Q also scaled by kScale.
// ---------------------------------------------------------------------------
__global__ void rope_kernel(__half* __restrict__ Q, __half* __restrict__ K) {
    const int t = blockIdx.x;
    const float ft = (float)t;
    for (int p = threadIdx.x; p < kH * 64; p += blockDim.x) {
        const int h = p >> 6;
        const int i = p & 63;
        const float inv = __expf(-(float)i * 0.14391157f);
        float s, c;
        sincosf(ft * inv, &s, &c);
        const size_t base = (size_t)t * kC + h * kD;
        {
            float x1 = __half2float(Q[base + i]);
            float x2 = __half2float(Q[base + 64 + i]);
            Q[base + i]      = __float2half_rn((x1 * c - x2 * s) * kScale);
            Q[base + 64 + i] = __float2half_rn((x2 * c + x1 * s) * kScale);
        }
        {
            float x1 = __half2float(K[base + i]);
            float x2 = __half2float(K[base + 64 + i]);
            K[base + i]      = __float2half_rn(x1 * c - x2 * s);
            K[base + 64 + i] = __float2half_rn(x2 * c + x1 * s);
        }
    }
}

// ---------------------------------------------------------------------------
// FA2-style fp16 block-sparse flash attention.
// One CTA per (q-block, head): 64 q rows, 128 threads / 4 warps, 2 CTAs/SM.
// Warp m-stripe = 16 rows (QK warp tile 16x64, PV 16x128) so softmax runs
// entirely in registers: S fragments -> 4-lane shuffle row reductions -> P
// repacked register-to-register into PV A-fragments. No S/P smem, no Cr.
// K and Vt double-buffered -> only 2 __syncthreads per tile.
// Q fragments hoisted (tile-invariant).
// allowed(qb,kb) = kb <= qb && (qb-kb <= 16 || kb < 2 || (kb & 3) == 0).
// ---------------------------------------------------------------------------
constexpr int AQLDH = 136;   // Q/K rows in halfs (68 words, conflict-free)
constexpr int AVLDH = 72;    // Vt rows in halfs (36 words, conflict-free)
constexpr int QS_OFF = 0;                           // 64*136*2 = 17408
constexpr int KS_OFF = QS_OFF + 64 * AQLDH * 2;     // 17408 (x2 bufs)
constexpr int KS_BUF = 64 * AQLDH * 2;              // 17408
constexpr int VT_OFF = KS_OFF + 2 * KS_BUF;         // 52224 (x2 bufs)
constexpr int VT_BUF = 128 * AVLDH * 2;             // 18432
constexpr int ATTN_SMEM_BYTES = VT_OFF + 2 * VT_BUF;  // 89088

__global__ __launch_bounds__(128, 2) void attn_h(const __half* __restrict__ Q,
                                                 const __half* __restrict__ K,
                                                 const __half* __restrict__ Vt,
                                                 __half* __restrict__ Ctx) {
    extern __shared__ char smc[];
    const uint32_t sb = smem_u32(smc);

    const int qb = (gridDim.x - 1) - blockIdx.x;   // heavy-first
    const int h = blockIdx.y;
    const int tid = threadIdx.x;
    const int lane = tid & 31;
    const int wid = tid >> 5;      // 0..3 -> rows wid*16..+15
    const int fr = lane >> 2;
    const int fc = lane & 3;

    auto is_allowed = [&](int t) {
        return (t <= qb) && (((qb - t) <= 16) || (t < 2) || ((t & 3) == 0));
    };

    auto issueK = [&](int t, int buf) {
        const uint32_t base = sb + KS_OFF + buf * KS_BUF;
#pragma unroll
        for (int j = 0; j < 8; j++) {
            const int idx = tid + j * 128;
            const int rr = idx >> 4;
            const int ch = idx & 15;
            cp_async16(base + (uint32_t)rr * (AQLDH * 2) + ch * 16,
                       &K[(size_t)(t * 64 + rr) * kC + h * kD + ch * 8]);
        }
        CP_COMMIT();
    };
    auto issueV = [&](int t, int buf) {
        const uint32_t base = sb + VT_OFF + buf * VT_BUF;
#pragma unroll
        for (int j = 0; j < 8; j++) {
            const int idx = tid + j * 128;
            const int rr = idx >> 3;     // dim 0..127
            const int ch = idx & 7;
            cp_async16(base + (uint32_t)rr * (AVLDH * 2) + ch * 16,
                       &Vt[(size_t)(h * kD + rr) * kT + t * 64 + ch * 8]);
        }
        CP_COMMIT();
    };

    // Prologue: Q (group), K0 (group), V0 (group)
#pragma unroll
    for (int j = 0; j < 8; j++) {
        const int idx = tid + j * 128;
        const int rr = idx >> 4;
        const int ch = idx & 15;
        cp_async16(sb + QS_OFF + (uint32_t)rr * (AQLDH * 2) + ch * 16,
                   &Q[(size_t)(qb * 64 + rr) * kC + h * kD + ch * 8]);
    }
    CP_COMMIT();
    issueK(0, 0);
    issueV(0, 0);

    // Q fragments (tile-invariant): wait for Q only (K0, V0 stay pending)
    asm volatile("cp.async.wait_group 2;" ::: "memory");
    __syncthreads();
    uint32_t aq[8][4];
    {
        const uint32_t* Qw = (const uint32_t*)(smc + QS_OFF);
        const int r0 = wid * 16 + fr;
#pragma unroll
        for (int kk = 0; kk < 8; kk++) {
            const int c0 = kk * 8 + fc;
            aq[kk][0] = Qw[r0 * 68 + c0];
            aq[kk][1] = Qw[(r0 + 8) * 68 + c0];
            aq[kk][2] = Qw[r0 * 68 + c0 + 4];
            aq[kk][3] = Qw[(r0 + 8) * 68 + c0 + 4];
        }
    }

    float m0 = -INFINITY, m1 = -INFINITY, l0 = 0.0f, l1 = 0.0f;
    float o[16][4];
#pragma unroll
    for (int ni = 0; ni < 16; ni++)
#pragma unroll
        for (int j = 0; j < 4; j++) o[ni][j] = 0.0f;

    int kb = 0, ib = 0;

    while (true) {
        int kbn = kb;
        for (int t = kb + 1; t <= qb; t++) {
            if (is_allowed(t)) { kbn = t; break; }
        }

        // wait for K(ib); V(ib) stays pending
        asm volatile("cp.async.wait_group 1;" ::: "memory");
        __syncthreads();

        // ---- S = Q @ K^T : warp tile 16x64, 8 k-steps ----
        const uint32_t* Kw =
            (const uint32_t*)(smc + KS_OFF + (ib & 1) * KS_BUF);
        float s[8][4];
#pragma unroll
        for (int ni = 0; ni < 8; ni++)
#pragma unroll
            for (int j = 0; j < 4; j++) s[ni][j] = 0.0f;

#pragma unroll
        for (int kk = 0; kk < 8; kk++) {
            const int c0 = kk * 8 + fc;
#pragma unroll
            for (int ni = 0; ni < 8; ni++) {
                const int n0 = ni * 8 + fr;
                uint32_t b[2];
                b[0] = Kw[n0 * 68 + c0];
                b[1] = Kw[n0 * 68 + c0 + 4];
                mma_f16(s[ni], aq[kk], b);
            }
        }

        // prefetch next K into the other buffer (its readers are >1 barrier back)
        issueK(kbn, (ib + 1) & 1);

        // ---- register softmax (rows wid*16+fr and +8; 16 cols each) ----
        uint32_t pa[4][4];
        {
            float lm0 = -INFINITY, lm1 = -INFINITY;
#pragma unroll
            for (int ni = 0; ni < 8; ni++) {
                lm0 = fmaxf(lm0, fmaxf(s[ni][0], s[ni][1]));
                lm1 = fmaxf(lm1, fmaxf(s[ni][2], s[ni][3]));
            }
            lm0 = fmaxf(lm0, __shfl_xor_sync(0xFFFFFFFFu, lm0, 1));
            lm0 = fmaxf(lm0, __shfl_xor_sync(0xFFFFFFFFu, lm0, 2));
            lm1 = fmaxf(lm1, __shfl_xor_sync(0xFFFFFFFFu, lm1, 1));
            lm1 = fmaxf(lm1, __shfl_xor_sync(0xFFFFFFFFu, lm1, 2));
            const float mn0 = fmaxf(m0, lm0);
            const float mn1 = fmaxf(m1, lm1);
            const float c0r = __expf(m0 - mn0);
            const float c1r = __expf(m1 - mn1);
            float rs0 = 0.0f, rs1 = 0.0f;
#pragma unroll
            for (int ni = 0; ni < 8; ni++) {
                const float e0 = __expf(s[ni][0] - mn0);
                const float e1 = __expf(s[ni][1] - mn0);
                const float e2 = __expf(s[ni][2] - mn1);
                const float e3 = __expf(s[ni][3] - mn1);
                rs0 += e0 + e1;
                rs1 += e2 + e3;
                const __half2 h01 = __floats2half2_rn(e0, e1);
                const __half2 h23 = __floats2half2_rn(e2, e3);
                const int kkk = ni >> 1;
                if ((ni & 1) == 0) {
                    pa[kkk][0] = *(const uint32_t*)&h01;
                    pa[kkk][1] = *(const uint32_t*)&h23;
                } else {
                    pa[kkk][2] = *(const uint32_t*)&h01;
                    pa[kkk][3] = *(const uint32_t*)&h23;
                }
            }
            rs0 += __shfl_xor_sync(0xFFFFFFFFu, rs0, 1);
            rs0 += __shfl_xor_sync(0xFFFFFFFFu, rs0, 2);
            rs1 += __shfl_xor_sync(0xFFFFFFFFu, rs1, 1);
            rs1 += __shfl_xor_sync(0xFFFFFFFFu, rs1, 2);
            l0 = l0 * c0r + rs0;
            l1 = l1 * c1r + rs1;
            m0 = mn0;
            m1 = mn1;
#pragma unroll
            for (int ni = 0; ni < 16; ni++) {
                o[ni][0] *= c0r; o[ni][1] *= c0r;
                o[ni][2] *= c1r; o[ni][3] *= c1r;
            }
        }

        // wait for V(ib); K(ib+1) stays pending
        asm volatile("cp.async.wait_group 1;" ::: "memory");
        __syncthreads();

        // ---- O += P @ V : warp tile 16x128, 4 k-steps ----
        const uint32_t* Vw =
            (const uint32_t*)(smc + VT_OFF + (ib & 1) * VT_BUF);
#pragma unroll
        for (int kk = 0; kk < 4; kk++) {
            const int c0 = kk * 8 + fc;
#pragma unroll
            for (int ni = 0; ni < 16; ni++) {
                const int n0 = ni * 8 + fr;
                uint32_t b[2];
                b[0] = Vw[n0 * 36 + c0];
                b[1] = Vw[n0 * 36 + c0 + 4];
                mma_f16(o[ni], pa[kk], b);
            }
        }

        // prefetch next V into the other buffer
        issueV(kbn, (ib + 1) & 1);

        if (kbn == kb) break;
        kb = kbn;
        ib++;
    }

    // Drain outstanding prefetches; epilogue is register-only.
    asm volatile("cp.async.wait_group 0;" ::: "memory");

    const float inv0 = 1.0f / l0;
    const float inv1 = 1.0f / l1;
    const int row0 = qb * 64 + wid * 16 + fr;
#pragma unroll
    for (int ni = 0; ni < 16; ni++) {
        const int col = h * kD + ni * 8 + fc * 2;
        __half2 h0 = __floats2half2_rn(o[ni][0] * inv0, o[ni][1] * inv0);
        __half2 h1 = __floats2half2_rn(o[ni][2] * inv1, o[ni][3] * inv1);
        *(__half2*)&Ctx[(size_t)row0 * kC + col] = h0;
        *(__half2*)&Ctx[(size_t)(row0 + 8) * kC + col] = h1;
    }
}

// ---------------------------------------------------------------------------
extern "C" void kernel_launch(void* const* d_in, const int* in_sizes, int n_in,
                              void* d_out, int out_size) {
    const float* x  = (const float*)d_in[0];
    const float* wq = (const float*)d_in[1];
    const float* wk = (const float*)d_in[2];
    const float* wv = (const float*)d_in[3];
    const float* wo = (const float*)d_in[4];
    float* out = (float*)d_out;

    __half *xh, *wh, *qh, *kh, *vh, *vt, *ch;
    cudaGetSymbolAddress((void**)&xh, g_xh);
    cudaGetSymbolAddress((void**)&wh, g_wh);
    cudaGetSymbolAddress((void**)&qh, g_qh);
    cudaGetSymbolAddress((void**)&kh, g_kh);
    cudaGetSymbolAddress((void**)&vh, g_vh);
    cudaGetSymbolAddress((void**)&vt, g_vt);
    cudaGetSymbolAddress((void**)&ch, g_ch);

    cudaFuncSetAttribute(gemm_h3, cudaFuncAttributeMaxDynamicSharedMemorySize,
                         GEMM_SMEM_BYTES);
    cudaFuncSetAttribute(attn_h, cudaFuncAttributeMaxDynamicSharedMemorySize,
                         ATTN_SMEM_BYTES);

    const int CC = kC * kC;

    convert_all<<<dim3(kT * kC / 4 / 256, 5), 256>>>(x, wq, wk, wv, wo, xh, wh);

    // Fused QKV projection: q,k,v all fp16 outputs
    gemm_h3<<<dim3(kC / 128, kT / 128, 3), 128, GEMM_SMEM_BYTES>>>(
        xh, wh + 0 * CC, wh + 1 * CC, wh + 2 * CC,
        qh, kh, vh, kT, kC, kC, 7u);

    rope_kernel<<<kT, 256>>>(qh, kh);
    transpose_v<<<dim3(kC / 64, kT / 64), 256>>>(vh, vt);

    attn_h<<<dim3(kT / 64, kH), 128, ATTN_SMEM_BYTES>>>(qh, kh, vt, ch);

    // Output projection: fp16 in, fp32 out
    gemm_h3<<<dim3(kC / 128, kT / 128, 1), 128, GEMM_SMEM_BYTES>>>(
        ch, wh + 3 * CC, wh + 3 * CC, wh + 3 * CC,
        out, out, out, kT, kC, kC, 0u);
}

// round 15
// speedup vs baseline: 2.1830x; 1.2085x over previous
#include <cuda_runtime.h>
#include <cuda_fp16.h>
#include <math.h>
#include <stdint.h>

// Problem constants
constexpr int kT = 4096;
constexpr int kC = 2048;
constexpr int kH = 16;
constexpr int kD = 128;
constexpr float kScale = 0.08838834764831845f;

// Scratch (device globals — no cudaMalloc allowed)
__device__ __half g_xh[kT * kC];        // x in fp16
__device__ __half g_wh[4 * kC * kC];    // wq,wk,wv,wo in fp16
__device__ __half g_qh[kT * kC];        // q fp16 (rope'd, scaled)
__device__ __half g_kh[kT * kC];        // k fp16 (rope'd)
__device__ __half g_vh[kT * kC];        // v fp16 [T][C]
__device__ __half g_ch[kT * kC];        // attention output fp16

// ---------------------------------------------------------------------------
__device__ __forceinline__ uint32_t smem_u32(const void* p) {
    uint32_t a;
    asm("{ .reg .u64 t; cvta.to.shared.u64 t, %1; cvt.u32.u64 %0, t; }"
        : "=r"(a) : "l"(p));
    return a;
}

__device__ __forceinline__ void cp_async16(uint32_t saddr, const void* gaddr) {
    asm volatile("cp.async.cg.shared.global [%0], [%1], 16;"
                 :: "r"(saddr), "l"(gaddr));
}
#define CP_COMMIT() asm volatile("cp.async.commit_group;" ::: "memory")

// mma.sync m16n8k16 fp16: D(16x8 f32) += A(16x16 f16) * B(16x8 f16)
__device__ __forceinline__ void mma_f16(float* d, const uint32_t* a,
                                        const uint32_t* b) {
    asm volatile(
        "mma.sync.aligned.m16n8k16.row.col.f32.f16.f16.f32 "
        "{%0,%1,%2,%3}, {%4,%5,%6,%7}, {%8,%9}, {%0,%1,%2,%3};"
        : "+f"(d[0]), "+f"(d[1]), "+f"(d[2]), "+f"(d[3])
        : "r"(a[0]), "r"(a[1]), "r"(a[2]), "r"(a[3]), "r"(b[0]), "r"(b[1]));
}

__device__ __forceinline__ void ldsm_x4(uint32_t& r0, uint32_t& r1,
                                        uint32_t& r2, uint32_t& r3,
                                        uint32_t addr) {
    asm volatile("ldmatrix.sync.aligned.m8n8.x4.shared.b16 {%0,%1,%2,%3}, [%4];"
                 : "=r"(r0), "=r"(r1), "=r"(r2), "=r"(r3) : "r"(addr));
}
__device__ __forceinline__ void ldsm_x4_t(uint32_t& r0, uint32_t& r1,
                                          uint32_t& r2, uint32_t& r3,
                                          uint32_t addr) {
    asm volatile("ldmatrix.sync.aligned.m8n8.x4.trans.shared.b16 {%0,%1,%2,%3}, [%4];"
                 : "=r"(r0), "=r"(r1), "=r"(r2), "=r"(r3) : "r"(addr));
}

// ---------------------------------------------------------------------------
// Fused fp32 -> fp16 conversion: y=0 -> x, y in 1..4 -> weights.
// ---------------------------------------------------------------------------
__global__ void convert_all(const float* __restrict__ x,
                            const float* __restrict__ wq,
                            const float* __restrict__ wk,
                            const float* __restrict__ wv,
                            const float* __restrict__ wo,
                            __half* __restrict__ xh, __half* __restrict__ wh) {
    const int y = blockIdx.y;
    const float* src;
    __half* dst;
    int n4;
    const int CC = kC * kC;
    if (y == 0) { src = x;  dst = xh;           n4 = kT * kC / 4; }
    else if (y == 1) { src = wq; dst = wh;          n4 = CC / 4; }
    else if (y == 2) { src = wk; dst = wh + CC;     n4 = CC / 4; }
    else if (y == 3) { src = wv; dst = wh + 2 * CC; n4 = CC / 4; }
    else             { src = wo; dst = wh + 3 * CC; n4 = CC / 4; }
    int i = blockIdx.x * blockDim.x + threadIdx.x;
    if (i < n4) {
        float4 v = ((const float4*)src)[i];
        __half2 h0 = __floats2half2_rn(v.x, v.y);
        __half2 h1 = __floats2half2_rn(v.z, v.w);
        uint2 u;
        u.x = *(uint32_t*)&h0;
        u.y = *(uint32_t*)&h1;
        *(uint2*)(dst + i * 4) = u;
    }
}

// ---------------------------------------------------------------------------
// FP16 tensor-core GEMM: C[m,n] = sum_k A[m,k]*B[n,k], fp32 accumulate.
// CTA tile 128x128x32, 4 warps, warp tile 64x64, m16n8k16, 3-stage cp.async.
// Fragments loaded via ldmatrix.x4 (row stride 80 B — bank-clean).
// ---------------------------------------------------------------------------
constexpr int GLDH = 40;
constexpr int GSTAGE_HALFS = 2 * 128 * GLDH;
constexpr int GEMM_SMEM_BYTES = 3 * GSTAGE_HALFS * 2;    // 61440

__global__ __launch_bounds__(128, 2) void gemm_h3(
    const __half* __restrict__ A,
    const __half* __restrict__ B0, const __half* __restrict__ B1,
    const __half* __restrict__ B2,
    void* __restrict__ C0, void* __restrict__ C1, void* __restrict__ C2,
    int M, int N, int K, unsigned halfMask) {
    const __half* B = (blockIdx.z == 0) ? B0 : (blockIdx.z == 1) ? B1 : B2;
    void* Cv = (blockIdx.z == 0) ? C0 : (blockIdx.z == 1) ? C1 : C2;
    const bool halfOut = (halfMask >> blockIdx.z) & 1u;

    extern __shared__ __half smh[];
    const uint32_t sb = smem_u32(smh);
    const int tid = threadIdx.x;
    const int lane = tid & 31;
    const int wid = tid >> 5;
    const int warp_m = wid & 1;
    const int warp_n = wid >> 1;
    const int bm = blockIdx.y * 128;
    const int bn = blockIdx.x * 128;

    float d[4][8][4];
#pragma unroll
    for (int mi = 0; mi < 4; mi++)
#pragma unroll
        for (int ni = 0; ni < 8; ni++)
#pragma unroll
            for (int j = 0; j < 4; j++) d[mi][ni][j] = 0.0f;

    const int nStages = K / 32;

    auto prefetch = [&](int s) {
        const int buf = s % 3;
        const uint32_t ab = sb + buf * GSTAGE_HALFS * 2;
        const uint32_t bb = ab + 128 * GLDH * 2;
        const int k0 = s * 32;
#pragma unroll
        for (int j = 0; j < 4; j++) {
            const int idx = tid + j * 128;
            const int row = idx >> 2;
            const int ch = idx & 3;
            const uint32_t soff = (uint32_t)row * 80 + ch * 16;
            cp_async16(ab + soff, &A[(size_t)(bm + row) * K + k0 + ch * 8]);
            cp_async16(bb + soff, &B[(size_t)(bn + row) * K + k0 + ch * 8]);
        }
        CP_COMMIT();
    };

    prefetch(0);
    prefetch(1);

    const int fr = lane >> 2;
    const int fc = lane & 3;
    const int l7 = lane & 7;
    const int lm = lane >> 3;

    // per-lane ldmatrix offsets (bytes within stage buffer)
    const uint32_t aoff = (uint32_t)(warp_m * 64 + (lm & 1) * 8 + l7) * 80
                          + (uint32_t)(lm >> 1) * 16;
    const uint32_t boff = 128u * 80u
                          + (uint32_t)(warp_n * 64 + (lm >> 1) * 8 + l7) * 80
                          + (uint32_t)(lm & 1) * 16;

    for (int s = 0; s < nStages; s++) {
        if (s < nStages - 1) {
            asm volatile("cp.async.wait_group 1;" ::: "memory");
        } else {
            asm volatile("cp.async.wait_group 0;" ::: "memory");
        }
        __syncthreads();
        if (s + 2 < nStages) prefetch(s + 2);

        const uint32_t sbuf = sb + (s % 3) * GSTAGE_HALFS * 2;

#pragma unroll
        for (int kk = 0; kk < 2; kk++) {
            uint32_t a[4][4];
#pragma unroll
            for (int mi = 0; mi < 4; mi++)
                ldsm_x4(a[mi][0], a[mi][1], a[mi][2], a[mi][3],
                        sbuf + aoff + mi * (16 * 80) + kk * 32);
            uint32_t b[8][2];
#pragma unroll
            for (int nj = 0; nj < 4; nj++)
                ldsm_x4(b[2 * nj][0], b[2 * nj][1], b[2 * nj + 1][0],
                        b[2 * nj + 1][1],
                        sbuf + boff + nj * (16 * 80) + kk * 32);
#pragma unroll
            for (int mi = 0; mi < 4; mi++)
#pragma unroll
                for (int ni = 0; ni < 8; ni++)
                    mma_f16(d[mi][ni], a[mi], b[ni]);
        }
    }

    if (halfOut) {
        __half* C = (__half*)Cv;
#pragma unroll
        for (int mi = 0; mi < 4; mi++) {
            const int row = bm + warp_m * 64 + mi * 16 + fr;
#pragma unroll
            for (int ni = 0; ni < 8; ni++) {
                const int col = bn + warp_n * 64 + ni * 8 + fc * 2;
                __half2 h0 = __floats2half2_rn(d[mi][ni][0], d[mi][ni][1]);
                __half2 h1 = __floats2half2_rn(d[mi][ni][2], d[mi][ni][3]);
                *(__half2*)&C[(size_t)row * N + col] = h0;
                *(__half2*)&C[(size_t)(row + 8) * N + col] = h1;
            }
        }
    } else {
        float* C = (float*)Cv;
#pragma unroll
        for (int mi = 0; mi < 4; mi++) {
            const int row = bm + warp_m * 64 + mi * 16 + fr;
#pragma unroll
            for (int ni = 0; ni < 8; ni++) {
                const int col = bn + warp_n * 64 + ni * 8 + fc * 2;
                *(float2*)&C[(size_t)row * N + col] =
                    make_float2(d[mi][ni][0], d[mi][ni][1]);
                *(float2*)&C[(size_t)(row + 8) * N + col] =
                    make_float2(d[mi][ni][2], d[mi][ni][3]);
            }
        }
    }
}

// ---------------------------------------------------------------------------
// RoPE in-place on fp16 Q and K laid out [T, H*D]. Q also scaled by kScale.
// ---------------------------------------------------------------------------
__global__ void rope_kernel(__half* __restrict__ Q, __half* __restrict__ K) {
    const int t = blockIdx.x;
    const float ft = (float)t;
    for (int p = threadIdx.x; p < kH * 64; p += blockDim.x) {
        const int h = p >> 6;
        const int i = p & 63;
        const float inv = __expf(-(float)i * 0.14391157f);
        float s, c;
        sincosf(ft * inv, &s, &c);
        const size_t base = (size_t)t * kC + h * kD;
        {
            float x1 = __half2float(Q[base + i]);
            float x2 = __half2float(Q[base + 64 + i]);
            Q[base + i]      = __float2half_rn((x1 * c - x2 * s) * kScale);
            Q[base + 64 + i] = __float2half_rn((x2 * c + x1 * s) * kScale);
        }
        {
            float x1 = __half2float(K[base + i]);
            float x2 = __half2float(K[base + 64 + i]);
            K[base + i]      = __float2half_rn(x1 * c - x2 * s);
            K[base + 64 + i] = __float2half_rn(x2 * c + x1 * s);
        }
    }
}

// ---------------------------------------------------------------------------
// FA2-style fp16 block-sparse flash attention with ldmatrix fragments.
// One CTA per (q-block, head): 64 q rows, 128 threads / 4 warps, 2 CTAs/SM.
// QK warp tile 16x64, PV 16x128; register softmax; P repacked in registers.
// V loaded ROW-MAJOR and fragmented via ldmatrix.x4.trans — no pre-transpose.
// K/V double-buffered; 2 __syncthreads per tile.
// allowed(qb,kb) = kb <= qb && (qb-kb <= 16 || kb < 2 || (kb & 3) == 0).
// ---------------------------------------------------------------------------
constexpr int ALDH = 136;    // Q/K/V rows in halfs (272 B)
constexpr int TILE_B = 64 * ALDH * 2;               // 17408 per tile
constexpr int QS_OFF = 0;
constexpr int KS_OFF = QS_OFF + TILE_B;             // x2 bufs
constexpr int VS_OFF = KS_OFF + 2 * TILE_B;         // x2 bufs
constexpr int ATTN_SMEM_BYTES = VS_OFF + 2 * TILE_B;  // 87040

__global__ __launch_bounds__(128, 2) void attn_h(const __half* __restrict__ Q,
                                                 const __half* __restrict__ K,
                                                 const __half* __restrict__ V,
                                                 __half* __restrict__ Ctx) {
    extern __shared__ char smc[];
    const uint32_t sb = smem_u32(smc);

    const int qb = (gridDim.x - 1) - blockIdx.x;   // heavy-first
    const int h = blockIdx.y;
    const int tid = threadIdx.x;
    const int lane = tid & 31;
    const int wid = tid >> 5;      // 0..3 -> rows wid*16..+15
    const int fr = lane >> 2;
    const int fc = lane & 3;
    const int l7 = lane & 7;
    const int lm = lane >> 3;

    auto is_allowed = [&](int t) {
        return (t <= qb) && (((qb - t) <= 16) || (t < 2) || ((t & 3) == 0));
    };

    auto issueTile = [&](const __half* src, int t, uint32_t base) {
#pragma unroll
        for (int j = 0; j < 8; j++) {
            const int idx = tid + j * 128;
            const int rr = idx >> 4;
            const int ch = idx & 15;
            cp_async16(base + (uint32_t)rr * (ALDH * 2) + ch * 16,
                       &src[(size_t)(t * 64 + rr) * kC + h * kD + ch * 8]);
        }
        CP_COMMIT();
    };

    // Prologue: Q (group), K0 (group), V0 (group)
    issueTile(Q, qb, sb + QS_OFF);
    issueTile(K, 0, sb + KS_OFF);
    issueTile(V, 0, sb + VS_OFF);

    // Q fragments (tile-invariant): wait for Q only
    asm volatile("cp.async.wait_group 2;" ::: "memory");
    __syncthreads();
    uint32_t aq[8][4];
    {
        const uint32_t qoff = sb + QS_OFF
            + (uint32_t)(wid * 16 + (lm & 1) * 8 + l7) * 272
            + (uint32_t)(lm >> 1) * 16;
#pragma unroll
        for (int kk = 0; kk < 8; kk++)
            ldsm_x4(aq[kk][0], aq[kk][1], aq[kk][2], aq[kk][3],
                    qoff + kk * 32);
    }

    // per-lane ldmatrix offsets within K / V tiles
    const uint32_t kfoff = (uint32_t)((lm >> 1) * 8 + l7) * 272
                           + (uint32_t)(lm & 1) * 16;
    const uint32_t vfoff = (uint32_t)((lm & 1) * 8 + l7) * 272
                           + (uint32_t)(lm >> 1) * 16;

    float m0 = -INFINITY, m1 = -INFINITY, l0 = 0.0f, l1 = 0.0f;
    float o[16][4];
#pragma unroll
    for (int ni = 0; ni < 16; ni++)
#pragma unroll
        for (int j = 0; j < 4; j++) o[ni][j] = 0.0f;

    int kb = 0, ib = 0;

    while (true) {
        int kbn = kb;
        for (int t = kb + 1; t <= qb; t++) {
            if (is_allowed(t)) { kbn = t; break; }
        }

        // wait for K(ib); V(ib) stays pending
        asm volatile("cp.async.wait_group 1;" ::: "memory");
        __syncthreads();

        // ---- S = Q @ K^T : warp tile 16x64, 8 k-steps ----
        const uint32_t kbase = sb + KS_OFF + (ib & 1) * TILE_B;
        float s[8][4];
#pragma unroll
        for (int ni = 0; ni < 8; ni++)
#pragma unroll
            for (int j = 0; j < 4; j++) s[ni][j] = 0.0f;

#pragma unroll
        for (int kk = 0; kk < 8; kk++) {
            uint32_t b[8][2];
#pragma unroll
            for (int nj = 0; nj < 4; nj++)
                ldsm_x4(b[2 * nj][0], b[2 * nj][1], b[2 * nj + 1][0],
                        b[2 * nj + 1][1],
                        kbase + kfoff + nj * (16 * 272) + kk * 32);
#pragma unroll
            for (int ni = 0; ni < 8; ni++)
                mma_f16(s[ni], aq[kk], b[ni]);
        }

        // prefetch next K into the other buffer
        issueTile(K, kbn, sb + KS_OFF + ((ib + 1) & 1) * TILE_B);

        // ---- register softmax (rows wid*16+fr and +8; 16 cols each) ----
        uint32_t pa[4][4];
        {
            float lm0 = -INFINITY, lm1 = -INFINITY;
#pragma unroll
            for (int ni = 0; ni < 8; ni++) {
                lm0 = fmaxf(lm0, fmaxf(s[ni][0], s[ni][1]));
                lm1 = fmaxf(lm1, fmaxf(s[ni][2], s[ni][3]));
            }
            lm0 = fmaxf(lm0, __shfl_xor_sync(0xFFFFFFFFu, lm0, 1));
            lm0 = fmaxf(lm0, __shfl_xor_sync(0xFFFFFFFFu, lm0, 2));
            lm1 = fmaxf(lm1, __shfl_xor_sync(0xFFFFFFFFu, lm1, 1));
            lm1 = fmaxf(lm1, __shfl_xor_sync(0xFFFFFFFFu, lm1, 2));
            const float mn0 = fmaxf(m0, lm0);
            const float mn1 = fmaxf(m1, lm1);
            const float c0r = __expf(m0 - mn0);
            const float c1r = __expf(m1 - mn1);
            float rs0 = 0.0f, rs1 = 0.0f;
#pragma unroll
            for (int ni = 0; ni < 8; ni++) {
                const float e0 = __expf(s[ni][0] - mn0);
                const float e1 = __expf(s[ni][1] - mn0);
                const float e2 = __expf(s[ni][2] - mn1);
                const float e3 = __expf(s[ni][3] - mn1);
                rs0 += e0 + e1;
                rs1 += e2 + e3;
                const __half2 h01 = __floats2half2_rn(e0, e1);
                const __half2 h23 = __floats2half2_rn(e2, e3);
                const int kkk = ni >> 1;
                if ((ni & 1) == 0) {
                    pa[kkk][0] = *(const uint32_t*)&h01;
                    pa[kkk][1] = *(const uint32_t*)&h23;
                } else {
                    pa[kkk][2] = *(const uint32_t*)&h01;
                    pa[kkk][3] = *(const uint32_t*)&h23;
                }
            }
            rs0 += __shfl_xor_sync(0xFFFFFFFFu, rs0, 1);
            rs0 += __shfl_xor_sync(0xFFFFFFFFu, rs0, 2);
            rs1 += __shfl_xor_sync(0xFFFFFFFFu, rs1, 1);
            rs1 += __shfl_xor_sync(0xFFFFFFFFu, rs1, 2);
            l0 = l0 * c0r + rs0;
            l1 = l1 * c1r + rs1;
            m0 = mn0;
            m1 = mn1;
#pragma unroll
            for (int ni = 0; ni < 16; ni++) {
                o[ni][0] *= c0r; o[ni][1] *= c0r;
                o[ni][2] *= c1r; o[ni][3] *= c1r;
            }
        }

        // wait for V(ib); K(ib+1) stays pending
        asm volatile("cp.async.wait_group 1;" ::: "memory");
        __syncthreads();

        // ---- O += P @ V : warp tile 16x128, 4 k-steps (V via trans-ldsm) ----
        const uint32_t vbase = sb + VS_OFF + (ib & 1) * TILE_B;
#pragma unroll
        for (int kk = 0; kk < 4; kk++) {
            uint32_t b[16][2];
#pragma unroll
            for (int nj = 0; nj < 8; nj++)
                ldsm_x4_t(b[2 * nj][0], b[2 * nj][1], b[2 * nj + 1][0],
                          b[2 * nj + 1][1],
                          vbase + vfoff + kk * (16 * 272) + nj * 32);
#pragma unroll
            for (int ni = 0; ni < 16; ni++)
                mma_f16(o[ni], pa[kk], b[ni]);
        }

        // prefetch next V into the other buffer
        issueTile(V, kbn, sb + VS_OFF + ((ib + 1) & 1) * TILE_B);

        if (kbn == kb) break;
        kb = kbn;
        ib++;
    }

    // Drain outstanding prefetches; epilogue is register-only.
    asm volatile("cp.async.wait_group 0;" ::: "memory");

    const float inv0 = 1.0f / l0;
    const float inv1 = 1.0f / l1;
    const int row0 = qb * 64 + wid * 16 + fr;
#pragma unroll
    for (int ni = 0; ni < 16; ni++) {
        const int col = h * kD + ni * 8 + fc * 2;
        __half2 h0 = __floats2half2_rn(o[ni][0] * inv0, o[ni][1] * inv0);
        __half2 h1 = __floats2half2_rn(o[ni][2] * inv1, o[ni][3] * inv1);
        *(__half2*)&Ctx[(size_t)row0 * kC + col] = h0;
        *(__half2*)&Ctx[(size_t)(row0 + 8) * kC + col] = h1;
    }
}

// ---------------------------------------------------------------------------
extern "C" void kernel_launch(void* const* d_in, const int* in_sizes, int n_in,
                              void* d_out, int out_size) {
    const float* x  = (const float*)d_in[0];
    const float* wq = (const float*)d_in[1];
    const float* wk = (const float*)d_in[2];
    const float* wv = (const float*)d_in[3];
    const float* wo = (const float*)d_in[4];
    float* out = (float*)d_out;

    __half *xh, *wh, *qh, *kh, *vh, *ch;
    cudaGetSymbolAddress((void**)&xh, g_xh);
    cudaGetSymbolAddress((void**)&wh, g_wh);
    cudaGetSymbolAddress((void**)&qh, g_qh);
    cudaGetSymbolAddress((void**)&kh, g_kh);
    cudaGetSymbolAddress((void**)&vh, g_vh);
    cudaGetSymbolAddress((void**)&ch, g_ch);

    cudaFuncSetAttribute(gemm_h3, cudaFuncAttributeMaxDynamicSharedMemorySize,
                         GEMM_SMEM_BYTES);
    cudaFuncSetAttribute(attn_h, cudaFuncAttributeMaxDynamicSharedMemorySize,
                         ATTN_SMEM_BYTES);

    const int CC = kC * kC;

    convert_all<<<dim3(kT * kC / 4 / 256, 5), 256>>>(x, wq, wk, wv, wo, xh, wh);

    // Fused QKV projection: q,k,v all fp16 outputs
    gemm_h3<<<dim3(kC / 128, kT / 128, 3), 128, GEMM_SMEM_BYTES>>>(
        xh, wh + 0 * CC, wh + 1 * CC, wh + 2 * CC,
        qh, kh, vh, kT, kC, kC, 7u);

    rope_kernel<<<kT, 256>>>(qh, kh);

    attn_h<<<dim3(kT / 64, kH), 128, ATTN_SMEM_BYTES>>>(qh, kh, vh, ch);

    // Output projection: fp16 in, fp32 out
    gemm_h3<<<dim3(kC / 128, kT / 128, 1), 128, GEMM_SMEM_BYTES>>>(
        ch, wh + 3 * CC, wh + 3 * CC, wh + 3 * CC,
        out, out, out, kT, kC, kC, 0u);
}